// round 4
// baseline (speedup 1.0000x reference)
#include <cuda_runtime.h>
#include <math.h>
#include <stdint.h>

// Problem constants
#define MM 8192           // B*L tokens
#define EE 1024
#define VV 64
#define NTT 2016
#define LN_EPS 1e-5f

// ---------------------------------------------------------------------------
// Scratch (device globals; no dynamic allocation allowed)
// ---------------------------------------------------------------------------
__device__ float g_h[(size_t)MM * EE];          // gelu output (pre-LN)
__device__ float g_theta[(size_t)MM * NTT];     // softplus(Theta)
__device__ int8_t g_hx_hi[(size_t)MM * EE], g_hx_lo[(size_t)MM * EE];
__device__ int8_t g_h_hi [(size_t)MM * EE], g_h_lo [(size_t)MM * EE];
__device__ int8_t g_Wd_hi[EE * EE],  g_Wd_lo[EE * EE];
__device__ int8_t g_Wt_hi[VV * EE],  g_Wt_lo[VV * EE];
__device__ int8_t g_WT_hi[NTT * EE], g_WT_lo[NTT * EE];
__device__ float g_rs_hx[MM], g_rs_h[MM];
__device__ float g_rs_Wd[EE], g_rs_Wt[VV], g_rs_WT[NTT];

// ---------------------------------------------------------------------------
// PTX helpers
// ---------------------------------------------------------------------------
__device__ __forceinline__ uint32_t smem_u32(const void* p) {
    return (uint32_t)__cvta_generic_to_shared(p);
}
__device__ __forceinline__ void cp16(uint32_t dst, const void* src, int sz) {
    asm volatile("cp.async.cg.shared.global [%0], [%1], 16, %2;"
                 :: "r"(dst), "l"(src), "r"(sz));
}
__device__ __forceinline__ void cp_commit() {
    asm volatile("cp.async.commit_group;" ::: "memory");
}
template<int N> __device__ __forceinline__ void cp_wait() {
    asm volatile("cp.async.wait_group %0;" :: "n"(N) : "memory");
}
__device__ __forceinline__ void ldsm4(uint32_t* r, uint32_t a) {
    asm volatile("ldmatrix.sync.aligned.m8n8.x4.shared.b16 {%0,%1,%2,%3}, [%4];"
        : "=r"(r[0]), "=r"(r[1]), "=r"(r[2]), "=r"(r[3]) : "r"(a));
}
__device__ __forceinline__ void ldsm2(uint32_t* r, uint32_t a) {
    asm volatile("ldmatrix.sync.aligned.m8n8.x2.shared.b16 {%0,%1}, [%2];"
        : "=r"(r[0]), "=r"(r[1]) : "r"(a));
}
__device__ __forceinline__ void imma(int* c, const uint32_t* a, uint32_t b0, uint32_t b1) {
    asm volatile(
        "mma.sync.aligned.m16n8k32.row.col.s32.s8.s8.s32 "
        "{%0,%1,%2,%3}, {%4,%5,%6,%7}, {%8,%9}, {%0,%1,%2,%3};"
        : "+r"(c[0]), "+r"(c[1]), "+r"(c[2]), "+r"(c[3])
        : "r"(a[0]), "r"(a[1]), "r"(a[2]), "r"(a[3]), "r"(b0), "r"(b1));
}

// ---------------------------------------------------------------------------
// Row quantization: x_row -> int8 hi/lo limbs + fp32 reciprocal scale.
// One 256-thread block per row of K=1024.
// ---------------------------------------------------------------------------
__device__ __forceinline__ float block_max_reduce(float m, float* red, int tid) {
#pragma unroll
    for (int o = 16; o; o >>= 1) m = fmaxf(m, __shfl_xor_sync(0xffffffffu, m, o));
    if ((tid & 31) == 0) red[tid >> 5] = m;
    __syncthreads();
    float t = (tid < 8) ? red[tid & 7] : 0.0f;
#pragma unroll
    for (int o = 4; o; o >>= 1) t = fmaxf(t, __shfl_xor_sync(0xffffffffu, t, o));
    t = __shfl_sync(0xffffffffu, t, 0);
    // broadcast across warps via smem
    if (tid == 0) red[0] = t;
    __syncthreads();
    return red[0];
}

__device__ __forceinline__ void quant4(const float* v, float s, char* hi, char* lo) {
#pragma unroll
    for (int k = 0; k < 4; ++k) {
        float q = v[k] * s;
        float ah = rintf(q);
        float al = rintf((q - ah) * 256.0f);
        al = fminf(fmaxf(al, -127.0f), 127.0f);
        hi[k] = (char)(int)ah;
        lo[k] = (char)(int)al;
    }
}

__global__ __launch_bounds__(256)
void quant_rows(const float* __restrict__ X, int8_t* __restrict__ hi,
                int8_t* __restrict__ lo, float* __restrict__ rs)
{
    const int row = blockIdx.x;
    const int tid = threadIdx.x;
    __shared__ float red[8];

    float4 v4 = ((const float4*)(X + (size_t)row * EE))[tid];
    float v[4] = {v4.x, v4.y, v4.z, v4.w};
    float m = fmaxf(fmaxf(fabsf(v[0]), fabsf(v[1])), fmaxf(fabsf(v[2]), fabsf(v[3])));
    m = block_max_reduce(m, red, tid);

    float s = (m > 0.0f) ? (127.0f / m) : 0.0f;
    if (tid == 0) rs[row] = m * (1.0f / 127.0f);

    char h[4], l[4];
    quant4(v, s, h, l);
    ((char4*)(hi + (size_t)row * EE))[tid] = *(char4*)h;
    ((char4*)(lo + (size_t)row * EE))[tid] = *(char4*)l;
}

// ---------------------------------------------------------------------------
// int8 3-term GEMM:  C[M,N] = epi( (A ~ qa*rsA) @ (B ~ qb*rsB)^T + bias )
// A,B int8 hi/lo limbs (row-major, K=1024). BM=BN=128, BK=64, 512 threads.
// 3-stage cp.async pipeline. EPI: 0 none, 1 gelu, 2 softplus
// ---------------------------------------------------------------------------
#define QBM 128
#define QBN 128
#define QBK 64
#define QSTR 80                  // smem bytes per row (64 + 16 pad)
#define QARR (128 * QSTR)        // 10240 per array
#define QSTAGE (4 * QARR)        // AH | AL | BH | BL
#define QSMEM (3 * QSTAGE)       // 122880

template<int EPI>
__global__ __launch_bounds__(512)
void gemm_q8(const int8_t* __restrict__ Ah, const int8_t* __restrict__ Al,
             const int8_t* __restrict__ Bh, const int8_t* __restrict__ Bl,
             const float* __restrict__ rsA, const float* __restrict__ rsB,
             const float* __restrict__ bias, float* __restrict__ C, int N)
{
    extern __shared__ char qsm[];
    const uint32_t sb = smem_u32(qsm);

    const int tid  = threadIdx.x;
    const int wid  = tid >> 5;
    const int lane = tid & 31;
    const int wm   = wid & 3;      // rows wm*32
    const int wn   = wid >> 2;     // cols wn*32
    const int bm   = blockIdx.x * QBM;
    const int bn   = blockIdx.y * QBN;

    // loader coords: 512 threads, 128 rows x 4 chunks of 16B
    const int lrow = tid >> 2;
    const int lch  = (tid & 3) * 16;
    const int gn   = bn + lrow;
    const int bvalid = (gn < N) ? 16 : 0;
    const int gnc  = (gn < N) ? gn : 0;
    const size_t aoff = (size_t)(bm + lrow) * EE + lch;
    const size_t boff = (size_t)gnc * EE + lch;
    const uint32_t ldst = (uint32_t)(lrow * QSTR + lch);

    auto issue_stage = [&](int kt) {
        const uint32_t st = sb + (kt % 3) * QSTAGE;
        const int k0 = kt * QBK;
        cp16(st + 0 * QARR + ldst, Ah + aoff + k0, 16);
        cp16(st + 1 * QARR + ldst, Al + aoff + k0, 16);
        cp16(st + 2 * QARR + ldst, Bh + boff + k0, bvalid);
        cp16(st + 3 * QARR + ldst, Bl + boff + k0, bvalid);
        cp_commit();
    };

    int acc1[2][4][4], acc2[2][4][4];
#pragma unroll
    for (int mt = 0; mt < 2; ++mt)
#pragma unroll
        for (int jj = 0; jj < 4; ++jj)
#pragma unroll
            for (int q = 0; q < 4; ++q) { acc1[mt][jj][q] = 0; acc2[mt][jj][q] = 0; }

    issue_stage(0);
    issue_stage(1);
    issue_stage(2);

    const int nk = EE / QBK;   // 16
    // ldmatrix lane address components
    const int a_r   = (lane & 7) + ((lane >> 3) & 1) * 8;   // row within 16
    const int a_c   = (lane >> 4) * 16;                     // byte 0 / 16
    const int b_r   = lane & 7;
    const int b_c   = ((lane >> 3) & 1) * 16;

    for (int kt = 0; kt < nk; ++kt) {
        cp_wait<2>();
        __syncthreads();
        const uint32_t st = sb + (kt % 3) * QSTAGE;

#pragma unroll
        for (int ks = 0; ks < 2; ++ks) {
            uint32_t aH[2][4], aL[2][4];
#pragma unroll
            for (int mt = 0; mt < 2; ++mt) {
                const uint32_t ao = st + (wm * 32 + mt * 16 + a_r) * QSTR + ks * 32 + a_c;
                ldsm4(aH[mt], ao + 0 * QARR);
                ldsm4(aL[mt], ao + 1 * QARR);
            }
#pragma unroll
            for (int jj = 0; jj < 4; ++jj) {
                const uint32_t bo = st + (wn * 32 + jj * 8 + b_r) * QSTR + ks * 32 + b_c;
                uint32_t bH[2], bL[2];
                ldsm2(bH, bo + 2 * QARR);
                ldsm2(bL, bo + 3 * QARR);
#pragma unroll
                for (int mt = 0; mt < 2; ++mt) {
                    imma(acc1[mt][jj], aH[mt], bH[0], bH[1]);
                    imma(acc2[mt][jj], aH[mt], bL[0], bL[1]);
                    imma(acc2[mt][jj], aL[mt], bH[0], bH[1]);
                }
            }
        }

        __syncthreads();
        if (kt + 3 < nk) issue_stage(kt + 3);
        else cp_commit();   // keep group accounting consistent
    }

    // epilogue
    const int g   = lane >> 2;
    const int tig = lane & 3;
#pragma unroll
    for (int mt = 0; mt < 2; ++mt) {
        const int row0 = bm + wm * 32 + mt * 16 + g;
        const float ra0 = rsA[row0];
        const float ra8 = rsA[row0 + 8];
#pragma unroll
        for (int jj = 0; jj < 4; ++jj) {
            const int col = bn + wn * 32 + jj * 8 + 2 * tig;
            if (col < N) {
                const float rb0 = rsB[col], rb1 = rsB[col + 1];
                const float bb0 = bias[col], bb1 = bias[col + 1];
                float vals[4];
                vals[0] = ((float)acc1[mt][jj][0] + (float)acc2[mt][jj][0] * (1.0f/256.0f)) * ra0 * rb0 + bb0;
                vals[1] = ((float)acc1[mt][jj][1] + (float)acc2[mt][jj][1] * (1.0f/256.0f)) * ra0 * rb1 + bb1;
                vals[2] = ((float)acc1[mt][jj][2] + (float)acc2[mt][jj][2] * (1.0f/256.0f)) * ra8 * rb0 + bb0;
                vals[3] = ((float)acc1[mt][jj][3] + (float)acc2[mt][jj][3] * (1.0f/256.0f)) * ra8 * rb1 + bb1;
#pragma unroll
                for (int q = 0; q < 4; ++q) {
                    float x = vals[q];
                    if (EPI == 1) {
                        x = 0.5f * x * (1.0f + erff(x * 0.70710678118654752440f));
                    } else if (EPI == 2) {
                        x = fmaxf(x, 0.0f) + log1pf(expf(-fabsf(x)));
                    }
                    vals[q] = x;
                }
                *(float2*)&C[(size_t)row0 * N + col]       = make_float2(vals[0], vals[1]);
                *(float2*)&C[(size_t)(row0 + 8) * N + col] = make_float2(vals[2], vals[3]);
            }
        }
    }
}

// ---------------------------------------------------------------------------
// LayerNorm over rows of E=1024, fused with int8 hi/lo quantization.
// ---------------------------------------------------------------------------
__global__ __launch_bounds__(256)
void ln_quant_kernel(const float* __restrict__ h, const float* __restrict__ g,
                     const float* __restrict__ b,
                     int8_t* __restrict__ hi, int8_t* __restrict__ lo,
                     float* __restrict__ rs)
{
    const int row = blockIdx.x;
    const int tid = threadIdx.x;
    const float* p = h + (size_t)row * EE;

    float4 v = ((const float4*)p)[tid];

    __shared__ float red[8];
    __shared__ float mu_s, rstd_s;

    float s = v.x + v.y + v.z + v.w;
#pragma unroll
    for (int o = 16; o; o >>= 1) s += __shfl_xor_sync(0xffffffffu, s, o);
    if ((tid & 31) == 0) red[tid >> 5] = s;
    __syncthreads();
    if (tid < 32) {
        float t = (tid < 8) ? red[tid] : 0.0f;
#pragma unroll
        for (int o = 4; o; o >>= 1) t += __shfl_xor_sync(0xffffffffu, t, o);
        if (tid == 0) mu_s = t * (1.0f / EE);
    }
    __syncthreads();
    const float mu = mu_s;

    float dx = v.x - mu, dy = v.y - mu, dz = v.z - mu, dw = v.w - mu;
    float s2 = dx * dx + dy * dy + dz * dz + dw * dw;
#pragma unroll
    for (int o = 16; o; o >>= 1) s2 += __shfl_xor_sync(0xffffffffu, s2, o);
    __syncthreads();
    if ((tid & 31) == 0) red[tid >> 5] = s2;
    __syncthreads();
    if (tid < 32) {
        float t = (tid < 8) ? red[tid] : 0.0f;
#pragma unroll
        for (int o = 4; o; o >>= 1) t += __shfl_xor_sync(0xffffffffu, t, o);
        if (tid == 0) rstd_s = rsqrtf(t * (1.0f / EE) + LN_EPS);
    }
    __syncthreads();
    const float rstd = rstd_s;

    const int c = tid * 4;
    float4 gg = *(const float4*)&g[c];
    float4 bb = *(const float4*)&b[c];
    float o[4];
    o[0] = dx * rstd * gg.x + bb.x;
    o[1] = dy * rstd * gg.y + bb.y;
    o[2] = dz * rstd * gg.z + bb.z;
    o[3] = dw * rstd * gg.w + bb.w;

    // row max-abs for quantization
    float m = fmaxf(fmaxf(fabsf(o[0]), fabsf(o[1])), fmaxf(fabsf(o[2]), fabsf(o[3])));
    __syncthreads();   // protect red[] reuse
    m = block_max_reduce(m, red, tid);

    float qs = (m > 0.0f) ? (127.0f / m) : 0.0f;
    if (tid == 0) rs[row] = m * (1.0f / 127.0f);

    char hb[4], lb4[4];
    quant4(o, qs, hb, lb4);
    ((char4*)(hi + (size_t)row * EE))[tid] = *(char4*)hb;
    ((char4*)(lo + (size_t)row * EE))[tid] = *(char4*)lb4;
}

// ---------------------------------------------------------------------------
// Softmax (in-place) over rows of V=64. One warp per row, 8 rows per block.
// ---------------------------------------------------------------------------
__global__ __launch_bounds__(256)
void softmax_kernel(float* __restrict__ logits)
{
    const int row = blockIdx.x * 8 + (threadIdx.x >> 5);
    const int lane = threadIdx.x & 31;
    float* p = logits + (size_t)row * VV;

    float2 v = *(const float2*)&p[lane * 2];
    float m = fmaxf(v.x, v.y);
#pragma unroll
    for (int o = 16; o; o >>= 1) m = fmaxf(m, __shfl_xor_sync(0xffffffffu, m, o));
    float e0 = expf(v.x - m), e1 = expf(v.y - m);
    float s = e0 + e1;
#pragma unroll
    for (int o = 16; o; o >>= 1) s += __shfl_xor_sync(0xffffffffu, s, o);
    float inv = 1.0f / s;
    float2 o2; o2.x = e0 * inv; o2.y = e1 * inv;
    *(float2*)&p[lane * 2] = o2;
}

// ---------------------------------------------------------------------------
// Q assembly
// ---------------------------------------------------------------------------
__global__ __launch_bounds__(256)
void qasm_kernel(const float* __restrict__ theta, const float* __restrict__ pi,
                 float* __restrict__ Q)
{
    const int tok = blockIdx.x;
    __shared__ float th[NTT];
    __shared__ float spi[VV];
    __shared__ float rspi[VV];

    const int tid = threadIdx.x;
    const float* tp = theta + (size_t)tok * NTT;
    for (int i = tid; i < NTT / 4; i += 256)
        ((float4*)th)[i] = ((const float4*)tp)[i];
    if (tid < VV) {
        float p = pi[(size_t)tok * VV + tid];
        float sp = sqrtf(p);
        spi[tid] = sp;
        rspi[tid] = 1.0f / sp;
    }
    __syncthreads();

    const int i = tid >> 2;
    const int jb = (tid & 3) * 16;
    const float ri = rspi[i];
    const int offi = i * (127 - i) / 2;

    float vals[16];
    float s = 0.0f;
#pragma unroll
    for (int jj = 0; jj < 16; ++jj) {
        int j = jb + jj;
        float sv;
        if (j == i)      sv = 0.0f;
        else if (i < j)  sv = th[offi + j - i - 1];
        else             sv = th[j * (127 - j) / 2 + i - j - 1];
        float qv = sv * spi[j] * ri;
        vals[jj] = qv;
        s += qv;
    }
    s += __shfl_xor_sync(0xffffffffu, s, 1);
    s += __shfl_xor_sync(0xffffffffu, s, 2);

    float* out = Q + (size_t)tok * (VV * VV) + i * VV + jb;
#pragma unroll
    for (int jj = 0; jj < 16; ++jj)
        out[jj] = (jb + jj == i) ? -s : vals[jj];
}

// ---------------------------------------------------------------------------
// Launch
// ---------------------------------------------------------------------------
extern "C" void kernel_launch(void* const* d_in, const int* in_sizes, int n_in,
                              void* d_out, int out_size)
{
    const float* hx = (const float*)d_in[0];   // (B,L,E)
    const float* Wd = (const float*)d_in[1];   // (E,E)
    const float* bd = (const float*)d_in[2];
    const float* lg = (const float*)d_in[3];
    const float* lb = (const float*)d_in[4];
    const float* Wt = (const float*)d_in[5];   // (V,E)
    const float* bt = (const float*)d_in[6];
    const float* WT = (const float*)d_in[7];   // (NT,E)
    const float* bT = (const float*)d_in[8];

    float* out = (float*)d_out;
    float* Q  = out;
    float* pi = out + (size_t)MM * VV * VV;

    float *hbuf, *thbuf;
    int8_t *hxh, *hxl, *hh, *hl, *wdh, *wdl, *wth, *wtl, *wTh, *wTl;
    float *rs_hx, *rs_h, *rs_wd, *rs_wt, *rs_wT;
    cudaGetSymbolAddress((void**)&hbuf,  g_h);
    cudaGetSymbolAddress((void**)&thbuf, g_theta);
    cudaGetSymbolAddress((void**)&hxh, g_hx_hi);  cudaGetSymbolAddress((void**)&hxl, g_hx_lo);
    cudaGetSymbolAddress((void**)&hh,  g_h_hi);   cudaGetSymbolAddress((void**)&hl,  g_h_lo);
    cudaGetSymbolAddress((void**)&wdh, g_Wd_hi);  cudaGetSymbolAddress((void**)&wdl, g_Wd_lo);
    cudaGetSymbolAddress((void**)&wth, g_Wt_hi);  cudaGetSymbolAddress((void**)&wtl, g_Wt_lo);
    cudaGetSymbolAddress((void**)&wTh, g_WT_hi);  cudaGetSymbolAddress((void**)&wTl, g_WT_lo);
    cudaGetSymbolAddress((void**)&rs_hx, g_rs_hx);
    cudaGetSymbolAddress((void**)&rs_h,  g_rs_h);
    cudaGetSymbolAddress((void**)&rs_wd, g_rs_Wd);
    cudaGetSymbolAddress((void**)&rs_wt, g_rs_Wt);
    cudaGetSymbolAddress((void**)&rs_wT, g_rs_WT);

    cudaFuncSetAttribute(gemm_q8<0>, cudaFuncAttributeMaxDynamicSharedMemorySize, QSMEM);
    cudaFuncSetAttribute(gemm_q8<1>, cudaFuncAttributeMaxDynamicSharedMemorySize, QSMEM);
    cudaFuncSetAttribute(gemm_q8<2>, cudaFuncAttributeMaxDynamicSharedMemorySize, QSMEM);

    // 0) quantize inputs (per-row int8 hi/lo + scale)
    quant_rows<<<MM, 256>>>(hx, hxh, hxl, rs_hx);
    quant_rows<<<EE, 256>>>(Wd, wdh, wdl, rs_wd);
    quant_rows<<<VV, 256>>>(Wt, wth, wtl, rs_wt);
    quant_rows<<<NTT, 256>>>(WT, wTh, wTl, rs_wT);

    // 1) h = gelu(hx @ Wd^T + bd)   (fp32 out)
    gemm_q8<1><<<dim3(MM / QBM, EE / QBN), 512, QSMEM>>>(
        hxh, hxl, wdh, wdl, rs_hx, rs_wd, bd, hbuf, EE);

    // 2) LayerNorm + quantize h
    ln_quant_kernel<<<MM, 256>>>(hbuf, lg, lb, hh, hl, rs_h);

    // 3) logits = h @ Wt^T + bt -> softmax (in pi region)
    gemm_q8<0><<<dim3(MM / QBM, 1), 512, QSMEM>>>(
        hh, hl, wth, wtl, rs_h, rs_wt, bt, pi, VV);
    softmax_kernel<<<MM / 8, 256>>>(pi);

    // 4) Theta = softplus(h @ WT^T + bT)
    gemm_q8<2><<<dim3(MM / QBM, (NTT + QBN - 1) / QBN), 512, QSMEM>>>(
        hh, hl, wTh, wTl, rs_h, rs_wT, bT, thbuf, NTT);

    // 5) Assemble Q
    qasm_kernel<<<MM, 256>>>(thbuf, pi, Q);
}

// round 5
// speedup vs baseline: 2.3929x; 2.3929x over previous
#include <cuda_runtime.h>
#include <cuda_bf16.h>
#include <math.h>
#include <stdint.h>

// Problem constants
#define MM 8192           // B*L tokens
#define EE 1024
#define VV 64
#define NTT 2016
#define LN_EPS 1e-5f

// ---------------------------------------------------------------------------
// Scratch (device globals; no dynamic allocation allowed)
// ---------------------------------------------------------------------------
__device__ float g_h[(size_t)MM * EE];          // gelu output (pre-LN)
__device__ float g_theta[(size_t)MM * NTT];     // softplus(Theta)
__device__ __nv_bfloat16 g_hx_hi[(size_t)MM * EE], g_hx_lo[(size_t)MM * EE];
__device__ __nv_bfloat16 g_h_hi [(size_t)MM * EE], g_h_lo [(size_t)MM * EE];
__device__ __nv_bfloat16 g_Wd_hi[EE * EE],  g_Wd_lo[EE * EE];
__device__ __nv_bfloat16 g_Wt_hi[VV * EE],  g_Wt_lo[VV * EE];
__device__ __nv_bfloat16 g_WT_hi[NTT * EE], g_WT_lo[NTT * EE];

// ---------------------------------------------------------------------------
// PTX helpers
// ---------------------------------------------------------------------------
__device__ __forceinline__ uint32_t smem_u32(const void* p) {
    return (uint32_t)__cvta_generic_to_shared(p);
}
__device__ __forceinline__ void cp16(uint32_t dst, const void* src, int sz) {
    asm volatile("cp.async.cg.shared.global [%0], [%1], 16, %2;"
                 :: "r"(dst), "l"(src), "r"(sz));
}
__device__ __forceinline__ void cp_commit() {
    asm volatile("cp.async.commit_group;" ::: "memory");
}
template<int N> __device__ __forceinline__ void cp_wait() {
    asm volatile("cp.async.wait_group %0;" :: "n"(N) : "memory");
}
__device__ __forceinline__ void ldsm4(uint32_t* r, uint32_t a) {
    asm volatile("ldmatrix.sync.aligned.m8n8.x4.shared.b16 {%0,%1,%2,%3}, [%4];"
        : "=r"(r[0]), "=r"(r[1]), "=r"(r[2]), "=r"(r[3]) : "r"(a));
}
__device__ __forceinline__ void mma16816(float* c, const uint32_t* a,
                                         uint32_t b0, uint32_t b1) {
    asm volatile(
        "mma.sync.aligned.m16n8k16.row.col.f32.bf16.bf16.f32 "
        "{%0,%1,%2,%3}, {%4,%5,%6,%7}, {%8,%9}, {%0,%1,%2,%3};"
        : "+f"(c[0]), "+f"(c[1]), "+f"(c[2]), "+f"(c[3])
        : "r"(a[0]), "r"(a[1]), "r"(a[2]), "r"(a[3]), "r"(b0), "r"(b1));
}

// ---------------------------------------------------------------------------
// fp32 -> (bf16 hi, bf16 lo) split, vectorized float4
// ---------------------------------------------------------------------------
__global__ __launch_bounds__(256)
void split_kernel(const float* __restrict__ x, __nv_bfloat16* __restrict__ hi,
                  __nv_bfloat16* __restrict__ lo, int n4)
{
    int i = blockIdx.x * 256 + threadIdx.x;
    if (i >= n4) return;
    float4 v = ((const float4*)x)[i];
    __nv_bfloat16 h[4], l[4];
    float vv[4] = {v.x, v.y, v.z, v.w};
#pragma unroll
    for (int k = 0; k < 4; ++k) {
        h[k] = __float2bfloat16(vv[k]);
        l[k] = __float2bfloat16(vv[k] - __bfloat162float(h[k]));
    }
    ((uint2*)hi)[i] = *(uint2*)h;
    ((uint2*)lo)[i] = *(uint2*)l;
}

// ---------------------------------------------------------------------------
// bf16 3-term HMMA GEMM:  C[M,N] = epi(A[M,K] @ B[N,K]^T + bias[N])
// BM=128, BN template (256 big / 64 narrow), BK=64, 512 threads (16 warps).
// cp.async double-buffered smem, padded 144B rows.
// EPI: 0 none, 1 exact gelu, 2 softplus
// ---------------------------------------------------------------------------
#define HBM 128
#define HBK 64
#define HROWB 144                 // 64 bf16 = 128B + 16B pad

template<int EPI, int BN, int WN>
__global__ __launch_bounds__(512, 1)
void gemm_hmma(const __nv_bfloat16* __restrict__ Ah, const __nv_bfloat16* __restrict__ Al,
               const __nv_bfloat16* __restrict__ Bh, const __nv_bfloat16* __restrict__ Bl,
               const float* __restrict__ bias, float* __restrict__ C,
               int N, int K)
{
    constexpr int WM  = 16 / WN;        // warps in M
    constexpr int WTM = HBM / WM;       // warp tile M
    constexpr int WTN = BN / WN;        // warp tile N
    constexpr int MT  = WTM / 16;       // m16 steps
    constexpr int NJ  = WTN / 16;       // 16-col groups

    constexpr int A_BYTES = HBM * HROWB;        // 18432
    constexpr int B_BYTES = BN * HROWB;
    constexpr int AHOFF = 0;
    constexpr int ALOFF = A_BYTES;
    constexpr int BHOFF = 2 * A_BYTES;
    constexpr int BLOFF = 2 * A_BYTES + B_BYTES;
    constexpr int STAGE = 2 * A_BYTES + 2 * B_BYTES;

    extern __shared__ char hsm[];
    const uint32_t sb = smem_u32(hsm);

    const int tid  = threadIdx.x;
    const int wid  = tid >> 5;
    const int lane = tid & 31;
    const int wmb  = (wid % WM) * WTM;
    const int wnb  = (wid / WM) * WTN;
    const int bm   = blockIdx.x * HBM;
    const int bn   = blockIdx.y * BN;

    // loader: chunk c -> row c>>3, 16B part c&7
    auto issue_stage = [&](int kt) {
        const uint32_t st = sb + (kt & 1) * STAGE;
        const int k0 = kt * HBK;
#pragma unroll
        for (int it = 0; it < 2; ++it) {          // A: 1024 chunks
            int c = tid + it * 512;
            int row = c >> 3, part = c & 7;
            uint32_t dst = (uint32_t)(row * HROWB + part * 16);
            size_t src = (size_t)(bm + row) * K + k0 + part * 8;
            cp16(st + AHOFF + dst, Ah + src, 16);
            cp16(st + ALOFF + dst, Al + src, 16);
        }
#pragma unroll
        for (int it = 0; it < BN / 64; ++it) {    // B: BN*8 chunks
            int c = tid + it * 512;
            int row = c >> 3, part = c & 7;
            int gn = bn + row;
            int valid = (gn < N) ? 16 : 0;
            int gnc = (gn < N) ? gn : 0;
            uint32_t dst = (uint32_t)(row * HROWB + part * 16);
            size_t src = (size_t)gnc * K + k0 + part * 8;
            cp16(st + BHOFF + dst, Bh + src, valid);
            cp16(st + BLOFF + dst, Bl + src, valid);
        }
        cp_commit();
    };

    float acc[MT][WTN / 8][4];
#pragma unroll
    for (int i = 0; i < MT; ++i)
#pragma unroll
        for (int j = 0; j < WTN / 8; ++j)
#pragma unroll
            for (int q = 0; q < 4; ++q) acc[i][j][q] = 0.0f;

    issue_stage(0);

    const int nk = K / HBK;
    // ldsm lane addressing (bytes)
    const int a_row = lane & 15;
    const int a_cb  = (lane >> 4) * 16;
    const int b_row = ((lane >> 4) ? 8 : 0) + (lane & 7);
    const int b_cb  = (((lane >> 3) & 1) ? 16 : 0);

    for (int kt = 0; kt < nk; ++kt) {
        if (kt + 1 < nk) { issue_stage(kt + 1); cp_wait<1>(); }
        else             { cp_wait<0>(); }
        __syncthreads();
        const uint32_t st = sb + (kt & 1) * STAGE;

#pragma unroll
        for (int ks = 0; ks < 4; ++ks) {
            uint32_t aH[MT][4], aL[MT][4];
#pragma unroll
            for (int mt = 0; mt < MT; ++mt) {
                const uint32_t ao = st + (uint32_t)((wmb + mt * 16 + a_row) * HROWB
                                                    + ks * 32 + a_cb);
                ldsm4(aH[mt], ao + AHOFF);
                ldsm4(aL[mt], ao + ALOFF);
            }
#pragma unroll
            for (int jj = 0; jj < NJ; ++jj) {
                const uint32_t bo = st + (uint32_t)((wnb + jj * 16 + b_row) * HROWB
                                                    + ks * 32 + b_cb);
                uint32_t bH[4], bL[4];
                ldsm4(bH, bo + BHOFF);
                ldsm4(bL, bo + BLOFF);
#pragma unroll
                for (int mt = 0; mt < MT; ++mt) {
#pragma unroll
                    for (int sub = 0; sub < 2; ++sub) {
                        float* c = acc[mt][jj * 2 + sub];
                        mma16816(c, aH[mt], bH[sub * 2], bH[sub * 2 + 1]);
                        mma16816(c, aH[mt], bL[sub * 2], bL[sub * 2 + 1]);
                        mma16816(c, aL[mt], bH[sub * 2], bH[sub * 2 + 1]);
                    }
                }
            }
        }
        __syncthreads();
    }

    // epilogue
#pragma unroll
    for (int mt = 0; mt < MT; ++mt) {
        const int row = bm + wmb + mt * 16 + (lane >> 2);
#pragma unroll
        for (int nt = 0; nt < WTN / 8; ++nt) {
            const int col = bn + wnb + nt * 8 + (lane & 3) * 2;
            if (col < N) {
                const float b0 = bias[col], b1 = bias[col + 1];
                float vals[4];
                vals[0] = acc[mt][nt][0] + b0;
                vals[1] = acc[mt][nt][1] + b1;
                vals[2] = acc[mt][nt][2] + b0;
                vals[3] = acc[mt][nt][3] + b1;
#pragma unroll
                for (int q = 0; q < 4; ++q) {
                    float x = vals[q];
                    if (EPI == 1) {
                        x = 0.5f * x * (1.0f + erff(x * 0.70710678118654752440f));
                    } else if (EPI == 2) {
                        x = fmaxf(x, 0.0f) + log1pf(expf(-fabsf(x)));
                    }
                    vals[q] = x;
                }
                *(float2*)&C[(size_t)row * N + col]       = make_float2(vals[0], vals[1]);
                *(float2*)&C[(size_t)(row + 8) * N + col] = make_float2(vals[2], vals[3]);
            }
        }
    }
}

// ---------------------------------------------------------------------------
// LayerNorm over rows of E=1024, fused with bf16 hi/lo split of the output.
// ---------------------------------------------------------------------------
__global__ __launch_bounds__(256)
void ln_split_kernel(const float* __restrict__ h, const float* __restrict__ g,
                     const float* __restrict__ b,
                     __nv_bfloat16* __restrict__ hi, __nv_bfloat16* __restrict__ lo)
{
    const int row = blockIdx.x;
    const int tid = threadIdx.x;
    const float* p = h + (size_t)row * EE;

    float4 v = ((const float4*)p)[tid];

    __shared__ float red[8];
    __shared__ float mu_s, rstd_s;

    float s = v.x + v.y + v.z + v.w;
#pragma unroll
    for (int o = 16; o; o >>= 1) s += __shfl_xor_sync(0xffffffffu, s, o);
    if ((tid & 31) == 0) red[tid >> 5] = s;
    __syncthreads();
    if (tid < 32) {
        float t = (tid < 8) ? red[tid] : 0.0f;
#pragma unroll
        for (int o = 4; o; o >>= 1) t += __shfl_xor_sync(0xffffffffu, t, o);
        if (tid == 0) mu_s = t * (1.0f / EE);
    }
    __syncthreads();
    const float mu = mu_s;

    float dx = v.x - mu, dy = v.y - mu, dz = v.z - mu, dw = v.w - mu;
    float s2 = dx * dx + dy * dy + dz * dz + dw * dw;
#pragma unroll
    for (int o = 16; o; o >>= 1) s2 += __shfl_xor_sync(0xffffffffu, s2, o);
    __syncthreads();
    if ((tid & 31) == 0) red[tid >> 5] = s2;
    __syncthreads();
    if (tid < 32) {
        float t = (tid < 8) ? red[tid] : 0.0f;
#pragma unroll
        for (int o = 4; o; o >>= 1) t += __shfl_xor_sync(0xffffffffu, t, o);
        if (tid == 0) rstd_s = rsqrtf(t * (1.0f / EE) + LN_EPS);
    }
    __syncthreads();
    const float rstd = rstd_s;

    const int c = tid * 4;
    float4 gg = *(const float4*)&g[c];
    float4 bb = *(const float4*)&b[c];
    float o[4];
    o[0] = dx * rstd * gg.x + bb.x;
    o[1] = dy * rstd * gg.y + bb.y;
    o[2] = dz * rstd * gg.z + bb.z;
    o[3] = dw * rstd * gg.w + bb.w;

    __nv_bfloat16 hb[4], lb4[4];
#pragma unroll
    for (int k = 0; k < 4; ++k) {
        hb[k]  = __float2bfloat16(o[k]);
        lb4[k] = __float2bfloat16(o[k] - __bfloat162float(hb[k]));
    }
    ((uint2*)(hi + (size_t)row * EE))[tid] = *(uint2*)hb;
    ((uint2*)(lo + (size_t)row * EE))[tid] = *(uint2*)lb4;
}

// ---------------------------------------------------------------------------
// Softmax (in-place) over rows of V=64. One warp per row, 8 rows per block.
// ---------------------------------------------------------------------------
__global__ __launch_bounds__(256)
void softmax_kernel(float* __restrict__ logits)
{
    const int row = blockIdx.x * 8 + (threadIdx.x >> 5);
    const int lane = threadIdx.x & 31;
    float* p = logits + (size_t)row * VV;

    float2 v = *(const float2*)&p[lane * 2];
    float m = fmaxf(v.x, v.y);
#pragma unroll
    for (int o = 16; o; o >>= 1) m = fmaxf(m, __shfl_xor_sync(0xffffffffu, m, o));
    float e0 = expf(v.x - m), e1 = expf(v.y - m);
    float s = e0 + e1;
#pragma unroll
    for (int o = 16; o; o >>= 1) s += __shfl_xor_sync(0xffffffffu, s, o);
    float inv = 1.0f / s;
    float2 o2; o2.x = e0 * inv; o2.y = e1 * inv;
    *(float2*)&p[lane * 2] = o2;
}

// ---------------------------------------------------------------------------
// Q assembly
// ---------------------------------------------------------------------------
__global__ __launch_bounds__(256)
void qasm_kernel(const float* __restrict__ theta, const float* __restrict__ pi,
                 float* __restrict__ Q)
{
    const int tok = blockIdx.x;
    __shared__ float th[NTT];
    __shared__ float spi[VV];
    __shared__ float rspi[VV];

    const int tid = threadIdx.x;
    const float* tp = theta + (size_t)tok * NTT;
    for (int i = tid; i < NTT / 4; i += 256)
        ((float4*)th)[i] = ((const float4*)tp)[i];
    if (tid < VV) {
        float p = pi[(size_t)tok * VV + tid];
        float sp = sqrtf(p);
        spi[tid] = sp;
        rspi[tid] = 1.0f / sp;
    }
    __syncthreads();

    const int i = tid >> 2;
    const int jb = (tid & 3) * 16;
    const float ri = rspi[i];
    const int offi = i * (127 - i) / 2;

    float vals[16];
    float s = 0.0f;
#pragma unroll
    for (int jj = 0; jj < 16; ++jj) {
        int j = jb + jj;
        float sv;
        if (j == i)      sv = 0.0f;
        else if (i < j)  sv = th[offi + j - i - 1];
        else             sv = th[j * (127 - j) / 2 + i - j - 1];
        float qv = sv * spi[j] * ri;
        vals[jj] = qv;
        s += qv;
    }
    s += __shfl_xor_sync(0xffffffffu, s, 1);
    s += __shfl_xor_sync(0xffffffffu, s, 2);

    float* out = Q + (size_t)tok * (VV * VV) + i * VV + jb;
#pragma unroll
    for (int jj = 0; jj < 16; ++jj)
        out[jj] = (jb + jj == i) ? -s : vals[jj];
}

// ---------------------------------------------------------------------------
// Launch
// ---------------------------------------------------------------------------
#define SMEM_BIG  (2 * (2 * 128 * HROWB + 2 * 256 * HROWB))   // 221184
#define SMEM_SMALL (2 * (2 * 128 * HROWB + 2 * 64 * HROWB))   // 110592

extern "C" void kernel_launch(void* const* d_in, const int* in_sizes, int n_in,
                              void* d_out, int out_size)
{
    const float* hx = (const float*)d_in[0];   // (B,L,E)
    const float* Wd = (const float*)d_in[1];   // (E,E)
    const float* bd = (const float*)d_in[2];
    const float* lg = (const float*)d_in[3];
    const float* lb = (const float*)d_in[4];
    const float* Wt = (const float*)d_in[5];   // (V,E)
    const float* bt = (const float*)d_in[6];
    const float* WT = (const float*)d_in[7];   // (NT,E)
    const float* bT = (const float*)d_in[8];

    float* out = (float*)d_out;
    float* Q  = out;
    float* pi = out + (size_t)MM * VV * VV;

    float *hbuf, *thbuf;
    __nv_bfloat16 *hxh, *hxl, *hh, *hl, *wdh, *wdl, *wth, *wtl, *wTh, *wTl;
    cudaGetSymbolAddress((void**)&hbuf,  g_h);
    cudaGetSymbolAddress((void**)&thbuf, g_theta);
    cudaGetSymbolAddress((void**)&hxh, g_hx_hi);  cudaGetSymbolAddress((void**)&hxl, g_hx_lo);
    cudaGetSymbolAddress((void**)&hh,  g_h_hi);   cudaGetSymbolAddress((void**)&hl,  g_h_lo);
    cudaGetSymbolAddress((void**)&wdh, g_Wd_hi);  cudaGetSymbolAddress((void**)&wdl, g_Wd_lo);
    cudaGetSymbolAddress((void**)&wth, g_Wt_hi);  cudaGetSymbolAddress((void**)&wtl, g_Wt_lo);
    cudaGetSymbolAddress((void**)&wTh, g_WT_hi);  cudaGetSymbolAddress((void**)&wTl, g_WT_lo);

    cudaFuncSetAttribute((const void*)gemm_hmma<1, 256, 4>,
                         cudaFuncAttributeMaxDynamicSharedMemorySize, SMEM_BIG);
    cudaFuncSetAttribute((const void*)gemm_hmma<2, 256, 4>,
                         cudaFuncAttributeMaxDynamicSharedMemorySize, SMEM_BIG);
    cudaFuncSetAttribute((const void*)gemm_hmma<0, 64, 2>,
                         cudaFuncAttributeMaxDynamicSharedMemorySize, SMEM_SMALL);

    // 0) split inputs to bf16 hi/lo
    split_kernel<<<(MM * EE / 4 + 255) / 256, 256>>>(hx, hxh, hxl, MM * EE / 4);
    split_kernel<<<(EE * EE / 4 + 255) / 256, 256>>>(Wd, wdh, wdl, EE * EE / 4);
    split_kernel<<<(VV * EE / 4 + 255) / 256, 256>>>(Wt, wth, wtl, VV * EE / 4);
    split_kernel<<<(NTT * EE / 4 + 255) / 256, 256>>>(WT, wTh, wTl, NTT * EE / 4);

    // 1) h = gelu(hx @ Wd^T + bd)   (fp32 out)
    gemm_hmma<1, 256, 4><<<dim3(MM / HBM, EE / 256), 512, SMEM_BIG>>>(
        hxh, hxl, wdh, wdl, bd, hbuf, EE, EE);

    // 2) LayerNorm + split h to bf16 hi/lo
    ln_split_kernel<<<MM, 256>>>(hbuf, lg, lb, hh, hl);

    // 3) logits = h @ Wt^T + bt -> softmax (in pi region)
    gemm_hmma<0, 64, 2><<<dim3(MM / HBM, 1), 512, SMEM_SMALL>>>(
        hh, hl, wth, wtl, bt, pi, VV, EE);
    softmax_kernel<<<MM / 8, 256>>>(pi);

    // 4) Theta = softplus(h @ WT^T + bT)
    gemm_hmma<2, 256, 4><<<dim3(MM / HBM, (NTT + 255) / 256), 512, SMEM_BIG>>>(
        hh, hl, wTh, wTl, bT, thbuf, NTT, EE);

    // 5) Assemble Q
    qasm_kernel<<<MM, 256>>>(thbuf, pi, Q);
}

// round 6
// speedup vs baseline: 2.8725x; 1.2004x over previous
#include <cuda_runtime.h>
#include <cuda_bf16.h>
#include <math.h>
#include <stdint.h>

// Problem constants
#define MM 8192           // B*L tokens
#define EE 1024
#define VV 64
#define NTT 2016
#define LN_EPS 1e-5f

// ---------------------------------------------------------------------------
// Scratch (device globals; no dynamic allocation allowed)
// ---------------------------------------------------------------------------
__device__ float g_h[(size_t)MM * EE];          // gelu output (pre-LN)
__device__ float g_theta[(size_t)MM * NTT];     // softplus(Theta)
__device__ __nv_bfloat16 g_hx_hi[(size_t)MM * EE], g_hx_lo[(size_t)MM * EE];
__device__ __nv_bfloat16 g_h_hi [(size_t)MM * EE], g_h_lo [(size_t)MM * EE];
__device__ __nv_bfloat16 g_Wd_hi[EE * EE],  g_Wd_lo[EE * EE];
__device__ __nv_bfloat16 g_Wt_hi[VV * EE],  g_Wt_lo[VV * EE];
__device__ __nv_bfloat16 g_WT_hi[NTT * EE], g_WT_lo[NTT * EE];

// ---------------------------------------------------------------------------
// PTX helpers
// ---------------------------------------------------------------------------
__device__ __forceinline__ uint32_t smem_u32(const void* p) {
    return (uint32_t)__cvta_generic_to_shared(p);
}
__device__ __forceinline__ void cp16(uint32_t dst, const void* src, int sz) {
    asm volatile("cp.async.cg.shared.global [%0], [%1], 16, %2;"
                 :: "r"(dst), "l"(src), "r"(sz));
}
__device__ __forceinline__ void cp_commit() {
    asm volatile("cp.async.commit_group;" ::: "memory");
}
template<int N> __device__ __forceinline__ void cp_wait() {
    asm volatile("cp.async.wait_group %0;" :: "n"(N) : "memory");
}
__device__ __forceinline__ void ldsm4(uint32_t* r, uint32_t a) {
    asm volatile("ldmatrix.sync.aligned.m8n8.x4.shared.b16 {%0,%1,%2,%3}, [%4];"
        : "=r"(r[0]), "=r"(r[1]), "=r"(r[2]), "=r"(r[3]) : "r"(a));
}
__device__ __forceinline__ void mma16816(float* c, const uint32_t* a,
                                         uint32_t b0, uint32_t b1) {
    asm volatile(
        "mma.sync.aligned.m16n8k16.row.col.f32.bf16.bf16.f32 "
        "{%0,%1,%2,%3}, {%4,%5,%6,%7}, {%8,%9}, {%0,%1,%2,%3};"
        : "+f"(c[0]), "+f"(c[1]), "+f"(c[2]), "+f"(c[3])
        : "r"(a[0]), "r"(a[1]), "r"(a[2]), "r"(a[3]), "r"(b0), "r"(b1));
}

// ---------------------------------------------------------------------------
// fp32 -> (bf16 hi, bf16 lo) split, 8 elems/thread (uint4 stores)
// ---------------------------------------------------------------------------
__global__ __launch_bounds__(256)
void split_kernel(const float* __restrict__ x, __nv_bfloat16* __restrict__ hi,
                  __nv_bfloat16* __restrict__ lo, int n8)
{
    int i = blockIdx.x * 256 + threadIdx.x;
    if (i >= n8) return;
    float4 a = ((const float4*)x)[i * 2];
    float4 b = ((const float4*)x)[i * 2 + 1];
    float vv[8] = {a.x, a.y, a.z, a.w, b.x, b.y, b.z, b.w};
    __nv_bfloat16 h[8], l[8];
#pragma unroll
    for (int k = 0; k < 8; ++k) {
        h[k] = __float2bfloat16(vv[k]);
        l[k] = __float2bfloat16(vv[k] - __bfloat162float(h[k]));
    }
    ((uint4*)hi)[i] = *(uint4*)h;
    ((uint4*)lo)[i] = *(uint4*)l;
}

// ---------------------------------------------------------------------------
// bf16 3-term HMMA GEMM:  C[M,N] = epi(A[M,K] @ B[N,K]^T + bias[N])
// BM=128, BN template (256 big / 64 narrow), BK=64, 512 threads (16 warps).
// cp.async double-buffered smem, padded 144B rows.
// EPI: 0 none, 1 exact gelu, 2 softplus
// ---------------------------------------------------------------------------
#define HBM 128
#define HBK 64
#define HROWB 144                 // 64 bf16 = 128B + 16B pad

template<int EPI, int BN, int WN>
__global__ __launch_bounds__(512, 1)
void gemm_hmma(const __nv_bfloat16* __restrict__ Ah, const __nv_bfloat16* __restrict__ Al,
               const __nv_bfloat16* __restrict__ Bh, const __nv_bfloat16* __restrict__ Bl,
               const float* __restrict__ bias, float* __restrict__ C,
               int N, int K)
{
    constexpr int WM  = 16 / WN;        // warps in M
    constexpr int WTM = HBM / WM;       // warp tile M
    constexpr int WTN = BN / WN;        // warp tile N
    constexpr int MT  = WTM / 16;       // m16 steps
    constexpr int NJ  = WTN / 16;       // 16-col groups

    constexpr int A_BYTES = HBM * HROWB;
    constexpr int B_BYTES = BN * HROWB;
    constexpr int AHOFF = 0;
    constexpr int ALOFF = A_BYTES;
    constexpr int BHOFF = 2 * A_BYTES;
    constexpr int BLOFF = 2 * A_BYTES + B_BYTES;
    constexpr int STAGE = 2 * A_BYTES + 2 * B_BYTES;

    extern __shared__ char hsm[];
    const uint32_t sb = smem_u32(hsm);

    const int tid  = threadIdx.x;
    const int wid  = tid >> 5;
    const int lane = tid & 31;
    const int wmb  = (wid % WM) * WTM;
    const int wnb  = (wid / WM) * WTN;
    const int bm   = blockIdx.x * HBM;
    const int bn   = blockIdx.y * BN;

    auto issue_stage = [&](int kt) {
        const uint32_t st = sb + (kt & 1) * STAGE;
        const int k0 = kt * HBK;
#pragma unroll
        for (int it = 0; it < 2; ++it) {
            int c = tid + it * 512;
            int row = c >> 3, part = c & 7;
            uint32_t dst = (uint32_t)(row * HROWB + part * 16);
            size_t src = (size_t)(bm + row) * K + k0 + part * 8;
            cp16(st + AHOFF + dst, Ah + src, 16);
            cp16(st + ALOFF + dst, Al + src, 16);
        }
#pragma unroll
        for (int it = 0; it < BN / 64; ++it) {
            int c = tid + it * 512;
            int row = c >> 3, part = c & 7;
            int gn = bn + row;
            int valid = (gn < N) ? 16 : 0;
            int gnc = (gn < N) ? gn : 0;
            uint32_t dst = (uint32_t)(row * HROWB + part * 16);
            size_t src = (size_t)gnc * K + k0 + part * 8;
            cp16(st + BHOFF + dst, Bh + src, valid);
            cp16(st + BLOFF + dst, Bl + src, valid);
        }
        cp_commit();
    };

    float acc[MT][WTN / 8][4];
#pragma unroll
    for (int i = 0; i < MT; ++i)
#pragma unroll
        for (int j = 0; j < WTN / 8; ++j)
#pragma unroll
            for (int q = 0; q < 4; ++q) acc[i][j][q] = 0.0f;

    issue_stage(0);

    const int nk = K / HBK;
    const int a_row = lane & 15;
    const int a_cb  = (lane >> 4) * 16;
    const int b_row = ((lane >> 4) ? 8 : 0) + (lane & 7);
    const int b_cb  = (((lane >> 3) & 1) ? 16 : 0);

    for (int kt = 0; kt < nk; ++kt) {
        if (kt + 1 < nk) { issue_stage(kt + 1); cp_wait<1>(); }
        else             { cp_wait<0>(); }
        __syncthreads();
        const uint32_t st = sb + (kt & 1) * STAGE;

#pragma unroll
        for (int ks = 0; ks < 4; ++ks) {
            uint32_t aH[MT][4], aL[MT][4];
#pragma unroll
            for (int mt = 0; mt < MT; ++mt) {
                const uint32_t ao = st + (uint32_t)((wmb + mt * 16 + a_row) * HROWB
                                                    + ks * 32 + a_cb);
                ldsm4(aH[mt], ao + AHOFF);
                ldsm4(aL[mt], ao + ALOFF);
            }
#pragma unroll
            for (int jj = 0; jj < NJ; ++jj) {
                const uint32_t bo = st + (uint32_t)((wnb + jj * 16 + b_row) * HROWB
                                                    + ks * 32 + b_cb);
                uint32_t bH[4], bL[4];
                ldsm4(bH, bo + BHOFF);
                ldsm4(bL, bo + BLOFF);
#pragma unroll
                for (int mt = 0; mt < MT; ++mt) {
#pragma unroll
                    for (int sub = 0; sub < 2; ++sub) {
                        float* c = acc[mt][jj * 2 + sub];
                        mma16816(c, aH[mt], bH[sub * 2], bH[sub * 2 + 1]);
                        mma16816(c, aH[mt], bL[sub * 2], bL[sub * 2 + 1]);
                        mma16816(c, aL[mt], bH[sub * 2], bH[sub * 2 + 1]);
                    }
                }
            }
        }
        __syncthreads();
    }

    // epilogue
#pragma unroll
    for (int mt = 0; mt < MT; ++mt) {
        const int row = bm + wmb + mt * 16 + (lane >> 2);
#pragma unroll
        for (int nt = 0; nt < WTN / 8; ++nt) {
            const int col = bn + wnb + nt * 8 + (lane & 3) * 2;
            if (col < N) {
                const float b0 = bias[col], b1 = bias[col + 1];
                float vals[4];
                vals[0] = acc[mt][nt][0] + b0;
                vals[1] = acc[mt][nt][1] + b1;
                vals[2] = acc[mt][nt][2] + b0;
                vals[3] = acc[mt][nt][3] + b1;
#pragma unroll
                for (int q = 0; q < 4; ++q) {
                    float x = vals[q];
                    if (EPI == 1) {
                        x = 0.5f * x * (1.0f + erff(x * 0.70710678118654752440f));
                    } else if (EPI == 2) {
                        x = fmaxf(x, 0.0f) + log1pf(expf(-fabsf(x)));
                    }
                    vals[q] = x;
                }
                *(float2*)&C[(size_t)row * N + col]       = make_float2(vals[0], vals[1]);
                *(float2*)&C[(size_t)(row + 8) * N + col] = make_float2(vals[2], vals[3]);
            }
        }
    }
}

// ---------------------------------------------------------------------------
// LayerNorm over rows of E=1024, fused with bf16 hi/lo split of the output.
// 128 threads x 8 elems, uint4 stores.
// ---------------------------------------------------------------------------
__global__ __launch_bounds__(128)
void ln_split_kernel(const float* __restrict__ h, const float* __restrict__ g,
                     const float* __restrict__ b,
                     __nv_bfloat16* __restrict__ hi, __nv_bfloat16* __restrict__ lo)
{
    const int row = blockIdx.x;
    const int tid = threadIdx.x;
    const int wid = tid >> 5;
    const float* p = h + (size_t)row * EE;

    float4 v0 = ((const float4*)p)[tid * 2];
    float4 v1 = ((const float4*)p)[tid * 2 + 1];
    float v[8] = {v0.x, v0.y, v0.z, v0.w, v1.x, v1.y, v1.z, v1.w};

    __shared__ float red_a[4], red_b[4];

    float s = 0.0f;
#pragma unroll
    for (int k = 0; k < 8; ++k) s += v[k];
#pragma unroll
    for (int o = 16; o; o >>= 1) s += __shfl_xor_sync(0xffffffffu, s, o);
    if ((tid & 31) == 0) red_a[wid] = s;
    __syncthreads();
    const float mu = (red_a[0] + red_a[1] + red_a[2] + red_a[3]) * (1.0f / EE);

    float d[8];
    float s2 = 0.0f;
#pragma unroll
    for (int k = 0; k < 8; ++k) { d[k] = v[k] - mu; s2 += d[k] * d[k]; }
#pragma unroll
    for (int o = 16; o; o >>= 1) s2 += __shfl_xor_sync(0xffffffffu, s2, o);
    if ((tid & 31) == 0) red_b[wid] = s2;
    __syncthreads();
    const float rstd = rsqrtf((red_b[0] + red_b[1] + red_b[2] + red_b[3]) * (1.0f / EE)
                              + LN_EPS);

    const int c = tid * 8;
    float4 g0 = *(const float4*)&g[c], g1 = *(const float4*)&g[c + 4];
    float4 b0 = *(const float4*)&b[c], b1 = *(const float4*)&b[c + 4];
    float gg[8] = {g0.x, g0.y, g0.z, g0.w, g1.x, g1.y, g1.z, g1.w};
    float bb[8] = {b0.x, b0.y, b0.z, b0.w, b1.x, b1.y, b1.z, b1.w};

    __nv_bfloat16 hb[8], lb8[8];
#pragma unroll
    for (int k = 0; k < 8; ++k) {
        float o = d[k] * rstd * gg[k] + bb[k];
        hb[k]  = __float2bfloat16(o);
        lb8[k] = __float2bfloat16(o - __bfloat162float(hb[k]));
    }
    ((uint4*)(hi + (size_t)row * EE))[tid] = *(uint4*)hb;
    ((uint4*)(lo + (size_t)row * EE))[tid] = *(uint4*)lb8;
}

// ---------------------------------------------------------------------------
// Softmax (in-place) over rows of V=64. One warp per row, 8 rows per block.
// ---------------------------------------------------------------------------
__global__ __launch_bounds__(256)
void softmax_kernel(float* __restrict__ logits)
{
    const int row = blockIdx.x * 8 + (threadIdx.x >> 5);
    const int lane = threadIdx.x & 31;
    float* p = logits + (size_t)row * VV;

    float2 v = *(const float2*)&p[lane * 2];
    float m = fmaxf(v.x, v.y);
#pragma unroll
    for (int o = 16; o; o >>= 1) m = fmaxf(m, __shfl_xor_sync(0xffffffffu, m, o));
    float e0 = expf(v.x - m), e1 = expf(v.y - m);
    float s = e0 + e1;
#pragma unroll
    for (int o = 16; o; o >>= 1) s += __shfl_xor_sync(0xffffffffu, s, o);
    float inv = 1.0f / s;
    float2 o2; o2.x = e0 * inv; o2.y = e1 * inv;
    *(float2*)&p[lane * 2] = o2;
}

// ---------------------------------------------------------------------------
// Q assembly (float4 stores)
// ---------------------------------------------------------------------------
__global__ __launch_bounds__(256)
void qasm_kernel(const float* __restrict__ theta, const float* __restrict__ pi,
                 float* __restrict__ Q)
{
    const int tok = blockIdx.x;
    __shared__ float th[NTT];
    __shared__ float spi[VV];
    __shared__ float rspi[VV];

    const int tid = threadIdx.x;
    const float* tp = theta + (size_t)tok * NTT;
    for (int i = tid; i < NTT / 4; i += 256)
        ((float4*)th)[i] = ((const float4*)tp)[i];
    if (tid < VV) {
        float p = pi[(size_t)tok * VV + tid];
        float sp = sqrtf(p);
        spi[tid] = sp;
        rspi[tid] = 1.0f / sp;
    }
    __syncthreads();

    const int i = tid >> 2;
    const int jb = (tid & 3) * 16;
    const float ri = rspi[i];
    const int offi = i * (127 - i) / 2;

    float vals[16];
    float s = 0.0f;
#pragma unroll
    for (int jj = 0; jj < 16; ++jj) {
        int j = jb + jj;
        float sv;
        if (j == i)      sv = 0.0f;
        else if (i < j)  sv = th[offi + j - i - 1];
        else             sv = th[j * (127 - j) / 2 + i - j - 1];
        float qv = sv * spi[j] * ri;
        vals[jj] = qv;
        s += qv;
    }
    s += __shfl_xor_sync(0xffffffffu, s, 1);
    s += __shfl_xor_sync(0xffffffffu, s, 2);

    // diag substitution then vectorized store
    if (i >= jb && i < jb + 16) vals[i - jb] = -s;

    float4* out4 = (float4*)(Q + (size_t)tok * (VV * VV) + i * VV + jb);
#pragma unroll
    for (int q = 0; q < 4; ++q)
        out4[q] = make_float4(vals[q * 4], vals[q * 4 + 1],
                              vals[q * 4 + 2], vals[q * 4 + 3]);
}

// ---------------------------------------------------------------------------
// Launch (fork/join overlap: side stream for Wt/WT splits + GEMM2 + softmax)
// ---------------------------------------------------------------------------
#define SMEM_BIG  (2 * (2 * 128 * HROWB + 2 * 256 * HROWB))   // 221184
#define SMEM_SMALL (2 * (2 * 128 * HROWB + 2 * 64 * HROWB))   // 110592

extern "C" void kernel_launch(void* const* d_in, const int* in_sizes, int n_in,
                              void* d_out, int out_size)
{
    const float* hx = (const float*)d_in[0];   // (B,L,E)
    const float* Wd = (const float*)d_in[1];   // (E,E)
    const float* bd = (const float*)d_in[2];
    const float* lg = (const float*)d_in[3];
    const float* lb = (const float*)d_in[4];
    const float* Wt = (const float*)d_in[5];   // (V,E)
    const float* bt = (const float*)d_in[6];
    const float* WT = (const float*)d_in[7];   // (NT,E)
    const float* bT = (const float*)d_in[8];

    float* out = (float*)d_out;
    float* Q  = out;
    float* pi = out + (size_t)MM * VV * VV;

    float *hbuf, *thbuf;
    __nv_bfloat16 *hxh, *hxl, *hh, *hl, *wdh, *wdl, *wth, *wtl, *wTh, *wTl;
    cudaGetSymbolAddress((void**)&hbuf,  g_h);
    cudaGetSymbolAddress((void**)&thbuf, g_theta);
    cudaGetSymbolAddress((void**)&hxh, g_hx_hi);  cudaGetSymbolAddress((void**)&hxl, g_hx_lo);
    cudaGetSymbolAddress((void**)&hh,  g_h_hi);   cudaGetSymbolAddress((void**)&hl,  g_h_lo);
    cudaGetSymbolAddress((void**)&wdh, g_Wd_hi);  cudaGetSymbolAddress((void**)&wdl, g_Wd_lo);
    cudaGetSymbolAddress((void**)&wth, g_Wt_hi);  cudaGetSymbolAddress((void**)&wtl, g_Wt_lo);
    cudaGetSymbolAddress((void**)&wTh, g_WT_hi);  cudaGetSymbolAddress((void**)&wTl, g_WT_lo);

    cudaFuncSetAttribute((const void*)gemm_hmma<1, 256, 4>,
                         cudaFuncAttributeMaxDynamicSharedMemorySize, SMEM_BIG);
    cudaFuncSetAttribute((const void*)gemm_hmma<2, 256, 4>,
                         cudaFuncAttributeMaxDynamicSharedMemorySize, SMEM_BIG);
    cudaFuncSetAttribute((const void*)gemm_hmma<0, 64, 2>,
                         cudaFuncAttributeMaxDynamicSharedMemorySize, SMEM_SMALL);

    // side stream + events (created once; captured work identical every call)
    static cudaStream_t s1 = []{
        cudaStream_t s; cudaStreamCreateWithFlags(&s, cudaStreamNonBlocking); return s;
    }();
    static cudaEvent_t evFork = []{
        cudaEvent_t e; cudaEventCreateWithFlags(&e, cudaEventDisableTiming); return e;
    }();
    static cudaEvent_t evWT = []{
        cudaEvent_t e; cudaEventCreateWithFlags(&e, cudaEventDisableTiming); return e;
    }();
    static cudaEvent_t evLN = []{
        cudaEvent_t e; cudaEventCreateWithFlags(&e, cudaEventDisableTiming); return e;
    }();
    static cudaEvent_t evSM = []{
        cudaEvent_t e; cudaEventCreateWithFlags(&e, cudaEventDisableTiming); return e;
    }();

    // fork side stream
    cudaEventRecord(evFork, 0);
    cudaStreamWaitEvent(s1, evFork, 0);

    // side stream: Wt/WT splits (overlap with hx/Wd splits + GEMM1)
    split_kernel<<<(VV * EE / 8 + 255) / 256, 256, 0, s1>>>(Wt, wth, wtl, VV * EE / 8);
    split_kernel<<<(NTT * EE / 8 + 255) / 256, 256, 0, s1>>>(WT, wTh, wTl, NTT * EE / 8);
    cudaEventRecord(evWT, s1);

    // main stream: Wd/hx splits -> GEMM1 -> LN
    split_kernel<<<(EE * EE / 8 + 255) / 256, 256>>>(Wd, wdh, wdl, EE * EE / 8);
    split_kernel<<<(MM * EE / 8 + 255) / 256, 256>>>(hx, hxh, hxl, MM * EE / 8);
    gemm_hmma<1, 256, 4><<<dim3(MM / HBM, EE / 256), 512, SMEM_BIG>>>(
        hxh, hxl, wdh, wdl, bd, hbuf, EE, EE);
    ln_split_kernel<<<MM, 128>>>(hbuf, lg, lb, hh, hl);
    cudaEventRecord(evLN, 0);

    // side stream: GEMM2 + softmax (overlaps with GEMM3 on main)
    cudaStreamWaitEvent(s1, evLN, 0);
    gemm_hmma<0, 64, 2><<<dim3(MM / HBM, 1), 512, SMEM_SMALL, s1>>>(
        hh, hl, wth, wtl, bt, pi, VV, EE);
    softmax_kernel<<<MM / 8, 256, 0, s1>>>(pi);
    cudaEventRecord(evSM, s1);

    // main stream: GEMM3 (needs WT split), then join, then qasm
    cudaStreamWaitEvent(0, evWT, 0);
    gemm_hmma<2, 256, 4><<<dim3(MM / HBM, (NTT + 255) / 256), 512, SMEM_BIG>>>(
        hh, hl, wTh, wTl, bT, thbuf, NTT, EE);
    cudaStreamWaitEvent(0, evSM, 0);
    qasm_kernel<<<MM, 256>>>(thbuf, pi, Q);
}

// round 7
// speedup vs baseline: 3.3444x; 1.1643x over previous
#include <cuda_runtime.h>
#include <cuda_fp16.h>
#include <math.h>
#include <stdint.h>

// Problem constants
#define MM 8192           // B*L tokens
#define EE 1024
#define VV 64
#define NTT 2016
#define LN_EPS 1e-5f

// ---------------------------------------------------------------------------
// Scratch (device globals; no dynamic allocation allowed)
// ---------------------------------------------------------------------------
__device__ float g_h[(size_t)MM * EE];          // gelu output (pre-LN)
__device__ float g_theta[(size_t)MM * NTT];     // softplus(Theta)
__device__ __half g_hx_hi[(size_t)MM * EE], g_hx_lo[(size_t)MM * EE];
__device__ __half g_h_hi [(size_t)MM * EE], g_h_lo [(size_t)MM * EE];
__device__ __half g_Wd_hi[EE * EE],  g_Wd_lo[EE * EE];
__device__ __half g_Wt_hi[VV * EE],  g_Wt_lo[VV * EE];
__device__ __half g_WT_hi[NTT * EE], g_WT_lo[NTT * EE];

// ---------------------------------------------------------------------------
// PTX helpers
// ---------------------------------------------------------------------------
__device__ __forceinline__ uint32_t smem_u32(const void* p) {
    return (uint32_t)__cvta_generic_to_shared(p);
}
__device__ __forceinline__ void cp16(uint32_t dst, const void* src, int sz) {
    asm volatile("cp.async.cg.shared.global [%0], [%1], 16, %2;"
                 :: "r"(dst), "l"(src), "r"(sz));
}
__device__ __forceinline__ void cp_commit() {
    asm volatile("cp.async.commit_group;" ::: "memory");
}
template<int N> __device__ __forceinline__ void cp_wait() {
    asm volatile("cp.async.wait_group %0;" :: "n"(N) : "memory");
}
__device__ __forceinline__ void ldsm4(uint32_t* r, uint32_t a) {
    asm volatile("ldmatrix.sync.aligned.m8n8.x4.shared.b16 {%0,%1,%2,%3}, [%4];"
        : "=r"(r[0]), "=r"(r[1]), "=r"(r[2]), "=r"(r[3]) : "r"(a));
}
__device__ __forceinline__ void mma16816(float* c, const uint32_t* a,
                                         uint32_t b0, uint32_t b1) {
    asm volatile(
        "mma.sync.aligned.m16n8k16.row.col.f32.f16.f16.f32 "
        "{%0,%1,%2,%3}, {%4,%5,%6,%7}, {%8,%9}, {%0,%1,%2,%3};"
        : "+f"(c[0]), "+f"(c[1]), "+f"(c[2]), "+f"(c[3])
        : "r"(a[0]), "r"(a[1]), "r"(a[2]), "r"(a[3]), "r"(b0), "r"(b1));
}

// ---------------------------------------------------------------------------
// fp32 -> (fp16 hi, fp16 lo) split, 8 elems/thread (uint4 stores)
// ---------------------------------------------------------------------------
__global__ __launch_bounds__(256)
void split_kernel(const float* __restrict__ x, __half* __restrict__ hi,
                  __half* __restrict__ lo, int n8)
{
    int i = blockIdx.x * 256 + threadIdx.x;
    if (i >= n8) return;
    float4 a = ((const float4*)x)[i * 2];
    float4 b = ((const float4*)x)[i * 2 + 1];
    float vv[8] = {a.x, a.y, a.z, a.w, b.x, b.y, b.z, b.w};
    __half h[8], l[8];
#pragma unroll
    for (int k = 0; k < 8; ++k) {
        h[k] = __float2half_rn(vv[k]);
        l[k] = __float2half_rn(vv[k] - __half2float(h[k]));
    }
    ((uint4*)hi)[i] = *(uint4*)h;
    ((uint4*)lo)[i] = *(uint4*)l;
}

// ---------------------------------------------------------------------------
// fp16 multi-term HMMA GEMM:  C[M,N] = epi(A[M,K] @ B[N,K]^T + bias[N])
// BM=128, BN template (256 big / 64 narrow), BK=64, 512 threads (16 warps).
// TERMS=3: Ah*Bh + Ah*Bl + Al*Bh   (err ~2^-22)
// TERMS=2: Ah*Bh + Ah*Bl           (err ~2^-11; Theta path only)
// cp.async double-buffered smem, padded 144B rows.
// EPI: 0 none, 1 exact gelu, 2 softplus
// ---------------------------------------------------------------------------
#define HBM 128
#define HBK 64
#define HROWB 144                 // 64 fp16 = 128B + 16B pad

template<int EPI, int BN, int WN, int TERMS>
__global__ __launch_bounds__(512, 1)
void gemm_hmma(const __half* __restrict__ Ah, const __half* __restrict__ Al,
               const __half* __restrict__ Bh, const __half* __restrict__ Bl,
               const float* __restrict__ bias, float* __restrict__ C,
               int N, int K)
{
    constexpr int WM  = 16 / WN;        // warps in M
    constexpr int WTM = HBM / WM;       // warp tile M
    constexpr int WTN = BN / WN;        // warp tile N
    constexpr int MT  = WTM / 16;       // m16 steps
    constexpr int NJ  = WTN / 16;       // 16-col groups

    constexpr int A_BYTES = HBM * HROWB;
    constexpr int B_BYTES = BN * HROWB;
    constexpr int AHOFF = 0;
    constexpr int ALOFF = A_BYTES;
    constexpr int BHOFF = 2 * A_BYTES;
    constexpr int BLOFF = 2 * A_BYTES + B_BYTES;
    constexpr int STAGE = 2 * A_BYTES + 2 * B_BYTES;

    extern __shared__ char hsm[];
    const uint32_t sb = smem_u32(hsm);

    const int tid  = threadIdx.x;
    const int wid  = tid >> 5;
    const int lane = tid & 31;
    const int wmb  = (wid % WM) * WTM;
    const int wnb  = (wid / WM) * WTN;
    const int bm   = blockIdx.x * HBM;
    const int bn   = blockIdx.y * BN;

    auto issue_stage = [&](int kt) {
        const uint32_t st = sb + (kt & 1) * STAGE;
        const int k0 = kt * HBK;
#pragma unroll
        for (int it = 0; it < 2; ++it) {
            int c = tid + it * 512;
            int row = c >> 3, part = c & 7;
            uint32_t dst = (uint32_t)(row * HROWB + part * 16);
            size_t src = (size_t)(bm + row) * K + k0 + part * 8;
            cp16(st + AHOFF + dst, Ah + src, 16);
            if (TERMS == 3) cp16(st + ALOFF + dst, Al + src, 16);
        }
#pragma unroll
        for (int it = 0; it < BN / 64; ++it) {
            int c = tid + it * 512;
            int row = c >> 3, part = c & 7;
            int gn = bn + row;
            int valid = (gn < N) ? 16 : 0;
            int gnc = (gn < N) ? gn : 0;
            uint32_t dst = (uint32_t)(row * HROWB + part * 16);
            size_t src = (size_t)gnc * K + k0 + part * 8;
            cp16(st + BHOFF + dst, Bh + src, valid);
            cp16(st + BLOFF + dst, Bl + src, valid);
        }
        cp_commit();
    };

    float acc[MT][WTN / 8][4];
#pragma unroll
    for (int i = 0; i < MT; ++i)
#pragma unroll
        for (int j = 0; j < WTN / 8; ++j)
#pragma unroll
            for (int q = 0; q < 4; ++q) acc[i][j][q] = 0.0f;

    issue_stage(0);

    const int nk = K / HBK;
    const int a_row = lane & 15;
    const int a_cb  = (lane >> 4) * 16;
    const int b_row = ((lane >> 4) ? 8 : 0) + (lane & 7);
    const int b_cb  = (((lane >> 3) & 1) ? 16 : 0);

    for (int kt = 0; kt < nk; ++kt) {
        if (kt + 1 < nk) { issue_stage(kt + 1); cp_wait<1>(); }
        else             { cp_wait<0>(); }
        __syncthreads();
        const uint32_t st = sb + (kt & 1) * STAGE;

#pragma unroll
        for (int ks = 0; ks < 4; ++ks) {
            uint32_t aH[MT][4], aL[MT][4];
#pragma unroll
            for (int mt = 0; mt < MT; ++mt) {
                const uint32_t ao = st + (uint32_t)((wmb + mt * 16 + a_row) * HROWB
                                                    + ks * 32 + a_cb);
                ldsm4(aH[mt], ao + AHOFF);
                if (TERMS == 3) ldsm4(aL[mt], ao + ALOFF);
            }
#pragma unroll
            for (int jj = 0; jj < NJ; ++jj) {
                const uint32_t bo = st + (uint32_t)((wnb + jj * 16 + b_row) * HROWB
                                                    + ks * 32 + b_cb);
                uint32_t bH[4], bL[4];
                ldsm4(bH, bo + BHOFF);
                ldsm4(bL, bo + BLOFF);
#pragma unroll
                for (int mt = 0; mt < MT; ++mt) {
#pragma unroll
                    for (int sub = 0; sub < 2; ++sub) {
                        float* c = acc[mt][jj * 2 + sub];
                        mma16816(c, aH[mt], bH[sub * 2], bH[sub * 2 + 1]);
                        mma16816(c, aH[mt], bL[sub * 2], bL[sub * 2 + 1]);
                        if (TERMS == 3)
                            mma16816(c, aL[mt], bH[sub * 2], bH[sub * 2 + 1]);
                    }
                }
            }
        }
        __syncthreads();
    }

    // epilogue
#pragma unroll
    for (int mt = 0; mt < MT; ++mt) {
        const int row = bm + wmb + mt * 16 + (lane >> 2);
#pragma unroll
        for (int nt = 0; nt < WTN / 8; ++nt) {
            const int col = bn + wnb + nt * 8 + (lane & 3) * 2;
            if (col < N) {
                const float b0 = bias[col], b1 = bias[col + 1];
                float vals[4];
                vals[0] = acc[mt][nt][0] + b0;
                vals[1] = acc[mt][nt][1] + b1;
                vals[2] = acc[mt][nt][2] + b0;
                vals[3] = acc[mt][nt][3] + b1;
#pragma unroll
                for (int q = 0; q < 4; ++q) {
                    float x = vals[q];
                    if (EPI == 1) {
                        x = 0.5f * x * (1.0f + erff(x * 0.70710678118654752440f));
                    } else if (EPI == 2) {
                        x = fmaxf(x, 0.0f) + log1pf(expf(-fabsf(x)));
                    }
                    vals[q] = x;
                }
                *(float2*)&C[(size_t)row * N + col]       = make_float2(vals[0], vals[1]);
                *(float2*)&C[(size_t)(row + 8) * N + col] = make_float2(vals[2], vals[3]);
            }
        }
    }
}

// ---------------------------------------------------------------------------
// LayerNorm over rows of E=1024, fused with fp16 hi/lo split of the output.
// 128 threads x 8 elems, uint4 stores.
// ---------------------------------------------------------------------------
__global__ __launch_bounds__(128)
void ln_split_kernel(const float* __restrict__ h, const float* __restrict__ g,
                     const float* __restrict__ b,
                     __half* __restrict__ hi, __half* __restrict__ lo)
{
    const int row = blockIdx.x;
    const int tid = threadIdx.x;
    const int wid = tid >> 5;
    const float* p = h + (size_t)row * EE;

    float4 v0 = ((const float4*)p)[tid * 2];
    float4 v1 = ((const float4*)p)[tid * 2 + 1];
    float v[8] = {v0.x, v0.y, v0.z, v0.w, v1.x, v1.y, v1.z, v1.w};

    __shared__ float red_a[4], red_b[4];

    float s = 0.0f;
#pragma unroll
    for (int k = 0; k < 8; ++k) s += v[k];
#pragma unroll
    for (int o = 16; o; o >>= 1) s += __shfl_xor_sync(0xffffffffu, s, o);
    if ((tid & 31) == 0) red_a[wid] = s;
    __syncthreads();
    const float mu = (red_a[0] + red_a[1] + red_a[2] + red_a[3]) * (1.0f / EE);

    float d[8];
    float s2 = 0.0f;
#pragma unroll
    for (int k = 0; k < 8; ++k) { d[k] = v[k] - mu; s2 += d[k] * d[k]; }
#pragma unroll
    for (int o = 16; o; o >>= 1) s2 += __shfl_xor_sync(0xffffffffu, s2, o);
    if ((tid & 31) == 0) red_b[wid] = s2;
    __syncthreads();
    const float rstd = rsqrtf((red_b[0] + red_b[1] + red_b[2] + red_b[3]) * (1.0f / EE)
                              + LN_EPS);

    const int c = tid * 8;
    float4 g0 = *(const float4*)&g[c], g1 = *(const float4*)&g[c + 4];
    float4 b0 = *(const float4*)&b[c], b1 = *(const float4*)&b[c + 4];
    float gg[8] = {g0.x, g0.y, g0.z, g0.w, g1.x, g1.y, g1.z, g1.w};
    float bb[8] = {b0.x, b0.y, b0.z, b0.w, b1.x, b1.y, b1.z, b1.w};

    __half hb[8], lb8[8];
#pragma unroll
    for (int k = 0; k < 8; ++k) {
        float o = d[k] * rstd * gg[k] + bb[k];
        hb[k]  = __float2half_rn(o);
        lb8[k] = __float2half_rn(o - __half2float(hb[k]));
    }
    ((uint4*)(hi + (size_t)row * EE))[tid] = *(uint4*)hb;
    ((uint4*)(lo + (size_t)row * EE))[tid] = *(uint4*)lb8;
}

// ---------------------------------------------------------------------------
// Softmax (in-place) over rows of V=64. One warp per row, 8 rows per block.
// ---------------------------------------------------------------------------
__global__ __launch_bounds__(256)
void softmax_kernel(float* __restrict__ logits)
{
    const int row = blockIdx.x * 8 + (threadIdx.x >> 5);
    const int lane = threadIdx.x & 31;
    float* p = logits + (size_t)row * VV;

    float2 v = *(const float2*)&p[lane * 2];
    float m = fmaxf(v.x, v.y);
#pragma unroll
    for (int o = 16; o; o >>= 1) m = fmaxf(m, __shfl_xor_sync(0xffffffffu, m, o));
    float e0 = expf(v.x - m), e1 = expf(v.y - m);
    float s = e0 + e1;
#pragma unroll
    for (int o = 16; o; o >>= 1) s += __shfl_xor_sync(0xffffffffu, s, o);
    float inv = 1.0f / s;
    float2 o2; o2.x = e0 * inv; o2.y = e1 * inv;
    *(float2*)&p[lane * 2] = o2;
}

// ---------------------------------------------------------------------------
// Q assembly (float4 stores)
// ---------------------------------------------------------------------------
__global__ __launch_bounds__(256)
void qasm_kernel(const float* __restrict__ theta, const float* __restrict__ pi,
                 float* __restrict__ Q)
{
    const int tok = blockIdx.x;
    __shared__ float th[NTT];
    __shared__ float spi[VV];
    __shared__ float rspi[VV];

    const int tid = threadIdx.x;
    const float* tp = theta + (size_t)tok * NTT;
    for (int i = tid; i < NTT / 4; i += 256)
        ((float4*)th)[i] = ((const float4*)tp)[i];
    if (tid < VV) {
        float p = pi[(size_t)tok * VV + tid];
        float sp = sqrtf(p);
        spi[tid] = sp;
        rspi[tid] = 1.0f / sp;
    }
    __syncthreads();

    const int i = tid >> 2;
    const int jb = (tid & 3) * 16;
    const float ri = rspi[i];
    const int offi = i * (127 - i) / 2;

    float vals[16];
    float s = 0.0f;
#pragma unroll
    for (int jj = 0; jj < 16; ++jj) {
        int j = jb + jj;
        float sv;
        if (j == i)      sv = 0.0f;
        else if (i < j)  sv = th[offi + j - i - 1];
        else             sv = th[j * (127 - j) / 2 + i - j - 1];
        float qv = sv * spi[j] * ri;
        vals[jj] = qv;
        s += qv;
    }
    s += __shfl_xor_sync(0xffffffffu, s, 1);
    s += __shfl_xor_sync(0xffffffffu, s, 2);

    if (i >= jb && i < jb + 16) vals[i - jb] = -s;

    float4* out4 = (float4*)(Q + (size_t)tok * (VV * VV) + i * VV + jb);
#pragma unroll
    for (int q = 0; q < 4; ++q)
        out4[q] = make_float4(vals[q * 4], vals[q * 4 + 1],
                              vals[q * 4 + 2], vals[q * 4 + 3]);
}

// ---------------------------------------------------------------------------
// Launch (fork/join overlap: side stream for Wt/WT splits + GEMM2 + softmax)
// ---------------------------------------------------------------------------
#define SMEM_BIG  (2 * (2 * 128 * HROWB + 2 * 256 * HROWB))   // 221184
#define SMEM_SMALL (2 * (2 * 128 * HROWB + 2 * 64 * HROWB))   // 110592

extern "C" void kernel_launch(void* const* d_in, const int* in_sizes, int n_in,
                              void* d_out, int out_size)
{
    const float* hx = (const float*)d_in[0];   // (B,L,E)
    const float* Wd = (const float*)d_in[1];   // (E,E)
    const float* bd = (const float*)d_in[2];
    const float* lg = (const float*)d_in[3];
    const float* lb = (const float*)d_in[4];
    const float* Wt = (const float*)d_in[5];   // (V,E)
    const float* bt = (const float*)d_in[6];
    const float* WT = (const float*)d_in[7];   // (NT,E)
    const float* bT = (const float*)d_in[8];

    float* out = (float*)d_out;
    float* Q  = out;
    float* pi = out + (size_t)MM * VV * VV;

    float *hbuf, *thbuf;
    __half *hxh, *hxl, *hh, *hl, *wdh, *wdl, *wth, *wtl, *wTh, *wTl;
    cudaGetSymbolAddress((void**)&hbuf,  g_h);
    cudaGetSymbolAddress((void**)&thbuf, g_theta);
    cudaGetSymbolAddress((void**)&hxh, g_hx_hi);  cudaGetSymbolAddress((void**)&hxl, g_hx_lo);
    cudaGetSymbolAddress((void**)&hh,  g_h_hi);   cudaGetSymbolAddress((void**)&hl,  g_h_lo);
    cudaGetSymbolAddress((void**)&wdh, g_Wd_hi);  cudaGetSymbolAddress((void**)&wdl, g_Wd_lo);
    cudaGetSymbolAddress((void**)&wth, g_Wt_hi);  cudaGetSymbolAddress((void**)&wtl, g_Wt_lo);
    cudaGetSymbolAddress((void**)&wTh, g_WT_hi);  cudaGetSymbolAddress((void**)&wTl, g_WT_lo);

    cudaFuncSetAttribute((const void*)gemm_hmma<1, 256, 4, 3>,
                         cudaFuncAttributeMaxDynamicSharedMemorySize, SMEM_BIG);
    cudaFuncSetAttribute((const void*)gemm_hmma<2, 256, 4, 2>,
                         cudaFuncAttributeMaxDynamicSharedMemorySize, SMEM_BIG);
    cudaFuncSetAttribute((const void*)gemm_hmma<0, 64, 2, 3>,
                         cudaFuncAttributeMaxDynamicSharedMemorySize, SMEM_SMALL);

    // side stream + events (created once; captured work identical every call)
    static cudaStream_t s1 = []{
        cudaStream_t s; cudaStreamCreateWithFlags(&s, cudaStreamNonBlocking); return s;
    }();
    static cudaEvent_t evFork = []{
        cudaEvent_t e; cudaEventCreateWithFlags(&e, cudaEventDisableTiming); return e;
    }();
    static cudaEvent_t evWT = []{
        cudaEvent_t e; cudaEventCreateWithFlags(&e, cudaEventDisableTiming); return e;
    }();
    static cudaEvent_t evLN = []{
        cudaEvent_t e; cudaEventCreateWithFlags(&e, cudaEventDisableTiming); return e;
    }();
    static cudaEvent_t evSM = []{
        cudaEvent_t e; cudaEventCreateWithFlags(&e, cudaEventDisableTiming); return e;
    }();

    // fork side stream
    cudaEventRecord(evFork, 0);
    cudaStreamWaitEvent(s1, evFork, 0);

    // side stream: Wt/WT splits (overlap with hx/Wd splits + GEMM1)
    split_kernel<<<(VV * EE / 8 + 255) / 256, 256, 0, s1>>>(Wt, wth, wtl, VV * EE / 8);
    split_kernel<<<(NTT * EE / 8 + 255) / 256, 256, 0, s1>>>(WT, wTh, wTl, NTT * EE / 8);
    cudaEventRecord(evWT, s1);

    // main stream: Wd/hx splits -> GEMM1 -> LN
    split_kernel<<<(EE * EE / 8 + 255) / 256, 256>>>(Wd, wdh, wdl, EE * EE / 8);
    split_kernel<<<(MM * EE / 8 + 255) / 256, 256>>>(hx, hxh, hxl, MM * EE / 8);
    gemm_hmma<1, 256, 4, 3><<<dim3(MM / HBM, EE / 256), 512, SMEM_BIG>>>(
        hxh, hxl, wdh, wdl, bd, hbuf, EE, EE);
    ln_split_kernel<<<MM, 128>>>(hbuf, lg, lb, hh, hl);
    cudaEventRecord(evLN, 0);

    // side stream: GEMM2 + softmax (overlaps with GEMM3 on main)
    cudaStreamWaitEvent(s1, evLN, 0);
    gemm_hmma<0, 64, 2, 3><<<dim3(MM / HBM, 1), 512, SMEM_SMALL, s1>>>(
        hh, hl, wth, wtl, bt, pi, VV, EE);
    softmax_kernel<<<MM / 8, 256, 0, s1>>>(pi);
    cudaEventRecord(evSM, s1);

    // main stream: GEMM3 (needs WT split), then join, then qasm
    cudaStreamWaitEvent(0, evWT, 0);
    gemm_hmma<2, 256, 4, 2><<<dim3(MM / HBM, (NTT + 255) / 256), 512, SMEM_BIG>>>(
        hh, hl, wTh, wTl, bT, thbuf, NTT, EE);
    cudaStreamWaitEvent(0, evSM, 0);
    qasm_kernel<<<MM, 256>>>(thbuf, pi, Q);
}

// round 8
// speedup vs baseline: 3.6687x; 1.0970x over previous
#include <cuda_runtime.h>
#include <cuda_fp16.h>
#include <math.h>
#include <stdint.h>

// Problem constants
#define MM 8192           // B*L tokens
#define EE 1024
#define VV 64
#define NTT 2016
#define LN_EPS 1e-5f

// ---------------------------------------------------------------------------
// Scratch (device globals; no dynamic allocation allowed)
// ---------------------------------------------------------------------------
__device__ float g_h[(size_t)MM * EE];          // gelu output (pre-LN)
__device__ float g_theta[(size_t)MM * NTT];     // softplus(Theta)
__device__ __half g_hx_hi[(size_t)MM * EE];
__device__ __half g_h_hi [(size_t)MM * EE], g_h_lo [(size_t)MM * EE];
__device__ __half g_Wd_hi[EE * EE],  g_Wd_lo[EE * EE];
__device__ __half g_Wt_hi[VV * EE],  g_Wt_lo[VV * EE];
__device__ __half g_WT_hi[NTT * EE], g_WT_lo[NTT * EE];

// ---------------------------------------------------------------------------
// PTX helpers
// ---------------------------------------------------------------------------
__device__ __forceinline__ uint32_t smem_u32(const void* p) {
    return (uint32_t)__cvta_generic_to_shared(p);
}
__device__ __forceinline__ void cp16(uint32_t dst, const void* src, int sz) {
    asm volatile("cp.async.cg.shared.global [%0], [%1], 16, %2;"
                 :: "r"(dst), "l"(src), "r"(sz));
}
__device__ __forceinline__ void cp_commit() {
    asm volatile("cp.async.commit_group;" ::: "memory");
}
template<int N> __device__ __forceinline__ void cp_wait() {
    asm volatile("cp.async.wait_group %0;" :: "n"(N) : "memory");
}
__device__ __forceinline__ void ldsm4(uint32_t* r, uint32_t a) {
    asm volatile("ldmatrix.sync.aligned.m8n8.x4.shared.b16 {%0,%1,%2,%3}, [%4];"
        : "=r"(r[0]), "=r"(r[1]), "=r"(r[2]), "=r"(r[3]) : "r"(a));
}
__device__ __forceinline__ void mma16816(float* c, const uint32_t* a,
                                         uint32_t b0, uint32_t b1) {
    asm volatile(
        "mma.sync.aligned.m16n8k16.row.col.f32.f16.f16.f32 "
        "{%0,%1,%2,%3}, {%4,%5,%6,%7}, {%8,%9}, {%0,%1,%2,%3};"
        : "+f"(c[0]), "+f"(c[1]), "+f"(c[2]), "+f"(c[3])
        : "r"(a[0]), "r"(a[1]), "r"(a[2]), "r"(a[3]), "r"(b0), "r"(b1));
}

// ---------------------------------------------------------------------------
// fp32 -> (fp16 hi, fp16 lo) split, 8 elems/thread (uint4 stores)
// ---------------------------------------------------------------------------
__global__ __launch_bounds__(256)
void split_kernel(const float* __restrict__ x, __half* __restrict__ hi,
                  __half* __restrict__ lo, int n8)
{
    int i = blockIdx.x * 256 + threadIdx.x;
    if (i >= n8) return;
    float4 a = ((const float4*)x)[i * 2];
    float4 b = ((const float4*)x)[i * 2 + 1];
    float vv[8] = {a.x, a.y, a.z, a.w, b.x, b.y, b.z, b.w};
    __half h[8], l[8];
#pragma unroll
    for (int k = 0; k < 8; ++k) {
        h[k] = __float2half_rn(vv[k]);
        l[k] = __float2half_rn(vv[k] - __half2float(h[k]));
    }
    ((uint4*)hi)[i] = *(uint4*)h;
    ((uint4*)lo)[i] = *(uint4*)l;
}

// fp32 -> fp16 hi only (for A operands of 2-term GEMMs)
__global__ __launch_bounds__(256)
void split_hi_kernel(const float* __restrict__ x, __half* __restrict__ hi, int n8)
{
    int i = blockIdx.x * 256 + threadIdx.x;
    if (i >= n8) return;
    float4 a = ((const float4*)x)[i * 2];
    float4 b = ((const float4*)x)[i * 2 + 1];
    float vv[8] = {a.x, a.y, a.z, a.w, b.x, b.y, b.z, b.w};
    __half h[8];
#pragma unroll
    for (int k = 0; k < 8; ++k) h[k] = __float2half_rn(vv[k]);
    ((uint4*)hi)[i] = *(uint4*)h;
}

// ---------------------------------------------------------------------------
// fp16 multi-term HMMA GEMM:  C[M,N] = epi(A[M,K] @ B[N,K]^T + bias[N])
// BM=128, BN template (256 big / 64 narrow), BK=64, 512 threads (16 warps).
// TERMS=3: Ah*Bh + Ah*Bl + Al*Bh   (err ~2^-22)
// TERMS=2: Ah*Bh + Ah*Bl           (drops Al*B, measured err ~3e-5)
// cp.async double-buffered smem, padded 144B rows.
// EPI: 0 none, 1 exact gelu, 2 softplus
// ---------------------------------------------------------------------------
#define HBM 128
#define HBK 64
#define HROWB 144                 // 64 fp16 = 128B + 16B pad

template<int EPI, int BN, int WN, int TERMS>
__global__ __launch_bounds__(512, 1)
void gemm_hmma(const __half* __restrict__ Ah, const __half* __restrict__ Al,
               const __half* __restrict__ Bh, const __half* __restrict__ Bl,
               const float* __restrict__ bias, float* __restrict__ C,
               int N, int K)
{
    constexpr int WM  = 16 / WN;        // warps in M
    constexpr int WTM = HBM / WM;       // warp tile M
    constexpr int WTN = BN / WN;        // warp tile N
    constexpr int MT  = WTM / 16;       // m16 steps
    constexpr int NJ  = WTN / 16;       // 16-col groups

    constexpr int A_BYTES = HBM * HROWB;
    constexpr int B_BYTES = BN * HROWB;
    constexpr int AHOFF = 0;
    constexpr int ALOFF = A_BYTES;
    constexpr int BHOFF = 2 * A_BYTES;
    constexpr int BLOFF = 2 * A_BYTES + B_BYTES;
    constexpr int STAGE = 2 * A_BYTES + 2 * B_BYTES;

    extern __shared__ char hsm[];
    const uint32_t sb = smem_u32(hsm);

    const int tid  = threadIdx.x;
    const int wid  = tid >> 5;
    const int lane = tid & 31;
    const int wmb  = (wid % WM) * WTM;
    const int wnb  = (wid / WM) * WTN;
    const int bm   = blockIdx.x * HBM;
    const int bn   = blockIdx.y * BN;

    auto issue_stage = [&](int kt) {
        const uint32_t st = sb + (kt & 1) * STAGE;
        const int k0 = kt * HBK;
#pragma unroll
        for (int it = 0; it < 2; ++it) {
            int c = tid + it * 512;
            int row = c >> 3, part = c & 7;
            uint32_t dst = (uint32_t)(row * HROWB + part * 16);
            size_t src = (size_t)(bm + row) * K + k0 + part * 8;
            cp16(st + AHOFF + dst, Ah + src, 16);
            if (TERMS == 3) cp16(st + ALOFF + dst, Al + src, 16);
        }
#pragma unroll
        for (int it = 0; it < BN / 64; ++it) {
            int c = tid + it * 512;
            int row = c >> 3, part = c & 7;
            int gn = bn + row;
            int valid = (gn < N) ? 16 : 0;
            int gnc = (gn < N) ? gn : 0;
            uint32_t dst = (uint32_t)(row * HROWB + part * 16);
            size_t src = (size_t)gnc * K + k0 + part * 8;
            cp16(st + BHOFF + dst, Bh + src, valid);
            cp16(st + BLOFF + dst, Bl + src, valid);
        }
        cp_commit();
    };

    float acc[MT][WTN / 8][4];
#pragma unroll
    for (int i = 0; i < MT; ++i)
#pragma unroll
        for (int j = 0; j < WTN / 8; ++j)
#pragma unroll
            for (int q = 0; q < 4; ++q) acc[i][j][q] = 0.0f;

    issue_stage(0);

    const int nk = K / HBK;
    const int a_row = lane & 15;
    const int a_cb  = (lane >> 4) * 16;
    const int b_row = ((lane >> 4) ? 8 : 0) + (lane & 7);
    const int b_cb  = (((lane >> 3) & 1) ? 16 : 0);

    for (int kt = 0; kt < nk; ++kt) {
        if (kt + 1 < nk) { issue_stage(kt + 1); cp_wait<1>(); }
        else             { cp_wait<0>(); }
        __syncthreads();
        const uint32_t st = sb + (kt & 1) * STAGE;

#pragma unroll
        for (int ks = 0; ks < 4; ++ks) {
            uint32_t aH[MT][4], aL[MT][4];
#pragma unroll
            for (int mt = 0; mt < MT; ++mt) {
                const uint32_t ao = st + (uint32_t)((wmb + mt * 16 + a_row) * HROWB
                                                    + ks * 32 + a_cb);
                ldsm4(aH[mt], ao + AHOFF);
                if (TERMS == 3) ldsm4(aL[mt], ao + ALOFF);
            }
#pragma unroll
            for (int jj = 0; jj < NJ; ++jj) {
                const uint32_t bo = st + (uint32_t)((wnb + jj * 16 + b_row) * HROWB
                                                    + ks * 32 + b_cb);
                uint32_t bH[4], bL[4];
                ldsm4(bH, bo + BHOFF);
                ldsm4(bL, bo + BLOFF);
#pragma unroll
                for (int mt = 0; mt < MT; ++mt) {
#pragma unroll
                    for (int sub = 0; sub < 2; ++sub) {
                        float* c = acc[mt][jj * 2 + sub];
                        mma16816(c, aH[mt], bH[sub * 2], bH[sub * 2 + 1]);
                        mma16816(c, aH[mt], bL[sub * 2], bL[sub * 2 + 1]);
                        if (TERMS == 3)
                            mma16816(c, aL[mt], bH[sub * 2], bH[sub * 2 + 1]);
                    }
                }
            }
        }
        __syncthreads();
    }

    // epilogue
#pragma unroll
    for (int mt = 0; mt < MT; ++mt) {
        const int row = bm + wmb + mt * 16 + (lane >> 2);
#pragma unroll
        for (int nt = 0; nt < WTN / 8; ++nt) {
            const int col = bn + wnb + nt * 8 + (lane & 3) * 2;
            if (col < N) {
                const float b0 = bias[col], b1 = bias[col + 1];
                float vals[4];
                vals[0] = acc[mt][nt][0] + b0;
                vals[1] = acc[mt][nt][1] + b1;
                vals[2] = acc[mt][nt][2] + b0;
                vals[3] = acc[mt][nt][3] + b1;
#pragma unroll
                for (int q = 0; q < 4; ++q) {
                    float x = vals[q];
                    if (EPI == 1) {
                        x = 0.5f * x * (1.0f + erff(x * 0.70710678118654752440f));
                    } else if (EPI == 2) {
                        x = fmaxf(x, 0.0f) + log1pf(expf(-fabsf(x)));
                    }
                    vals[q] = x;
                }
                *(float2*)&C[(size_t)row * N + col]       = make_float2(vals[0], vals[1]);
                *(float2*)&C[(size_t)(row + 8) * N + col] = make_float2(vals[2], vals[3]);
            }
        }
    }
}

// ---------------------------------------------------------------------------
// LayerNorm over rows of E=1024, fused with fp16 hi/lo split of the output.
// 128 threads x 8 elems, uint4 stores.
// ---------------------------------------------------------------------------
__global__ __launch_bounds__(128)
void ln_split_kernel(const float* __restrict__ h, const float* __restrict__ g,
                     const float* __restrict__ b,
                     __half* __restrict__ hi, __half* __restrict__ lo)
{
    const int row = blockIdx.x;
    const int tid = threadIdx.x;
    const int wid = tid >> 5;
    const float* p = h + (size_t)row * EE;

    float4 v0 = ((const float4*)p)[tid * 2];
    float4 v1 = ((const float4*)p)[tid * 2 + 1];
    float v[8] = {v0.x, v0.y, v0.z, v0.w, v1.x, v1.y, v1.z, v1.w};

    __shared__ float red_a[4], red_b[4];

    float s = 0.0f;
#pragma unroll
    for (int k = 0; k < 8; ++k) s += v[k];
#pragma unroll
    for (int o = 16; o; o >>= 1) s += __shfl_xor_sync(0xffffffffu, s, o);
    if ((tid & 31) == 0) red_a[wid] = s;
    __syncthreads();
    const float mu = (red_a[0] + red_a[1] + red_a[2] + red_a[3]) * (1.0f / EE);

    float d[8];
    float s2 = 0.0f;
#pragma unroll
    for (int k = 0; k < 8; ++k) { d[k] = v[k] - mu; s2 += d[k] * d[k]; }
#pragma unroll
    for (int o = 16; o; o >>= 1) s2 += __shfl_xor_sync(0xffffffffu, s2, o);
    if ((tid & 31) == 0) red_b[wid] = s2;
    __syncthreads();
    const float rstd = rsqrtf((red_b[0] + red_b[1] + red_b[2] + red_b[3]) * (1.0f / EE)
                              + LN_EPS);

    const int c = tid * 8;
    float4 g0 = *(const float4*)&g[c], g1 = *(const float4*)&g[c + 4];
    float4 b0 = *(const float4*)&b[c], b1 = *(const float4*)&b[c + 4];
    float gg[8] = {g0.x, g0.y, g0.z, g0.w, g1.x, g1.y, g1.z, g1.w};
    float bb[8] = {b0.x, b0.y, b0.z, b0.w, b1.x, b1.y, b1.z, b1.w};

    __half hb[8], lb8[8];
#pragma unroll
    for (int k = 0; k < 8; ++k) {
        float o = d[k] * rstd * gg[k] + bb[k];
        hb[k]  = __float2half_rn(o);
        lb8[k] = __float2half_rn(o - __half2float(hb[k]));
    }
    ((uint4*)(hi + (size_t)row * EE))[tid] = *(uint4*)hb;
    ((uint4*)(lo + (size_t)row * EE))[tid] = *(uint4*)lb8;
}

// ---------------------------------------------------------------------------
// Softmax (in-place) over rows of V=64. One warp per row, 8 rows per block.
// ---------------------------------------------------------------------------
__global__ __launch_bounds__(256)
void softmax_kernel(float* __restrict__ logits)
{
    const int row = blockIdx.x * 8 + (threadIdx.x >> 5);
    const int lane = threadIdx.x & 31;
    float* p = logits + (size_t)row * VV;

    float2 v = *(const float2*)&p[lane * 2];
    float m = fmaxf(v.x, v.y);
#pragma unroll
    for (int o = 16; o; o >>= 1) m = fmaxf(m, __shfl_xor_sync(0xffffffffu, m, o));
    float e0 = expf(v.x - m), e1 = expf(v.y - m);
    float s = e0 + e1;
#pragma unroll
    for (int o = 16; o; o >>= 1) s += __shfl_xor_sync(0xffffffffu, s, o);
    float inv = 1.0f / s;
    float2 o2; o2.x = e0 * inv; o2.y = e1 * inv;
    *(float2*)&p[lane * 2] = o2;
}

// ---------------------------------------------------------------------------
// Q assembly (float4 stores)
// ---------------------------------------------------------------------------
__global__ __launch_bounds__(256)
void qasm_kernel(const float* __restrict__ theta, const float* __restrict__ pi,
                 float* __restrict__ Q)
{
    const int tok = blockIdx.x;
    __shared__ float th[NTT];
    __shared__ float spi[VV];
    __shared__ float rspi[VV];

    const int tid = threadIdx.x;
    const float* tp = theta + (size_t)tok * NTT;
    for (int i = tid; i < NTT / 4; i += 256)
        ((float4*)th)[i] = ((const float4*)tp)[i];
    if (tid < VV) {
        float p = pi[(size_t)tok * VV + tid];
        float sp = sqrtf(p);
        spi[tid] = sp;
        rspi[tid] = 1.0f / sp;
    }
    __syncthreads();

    const int i = tid >> 2;
    const int jb = (tid & 3) * 16;
    const float ri = rspi[i];
    const int offi = i * (127 - i) / 2;

    float vals[16];
    float s = 0.0f;
#pragma unroll
    for (int jj = 0; jj < 16; ++jj) {
        int j = jb + jj;
        float sv;
        if (j == i)      sv = 0.0f;
        else if (i < j)  sv = th[offi + j - i - 1];
        else             sv = th[j * (127 - j) / 2 + i - j - 1];
        float qv = sv * spi[j] * ri;
        vals[jj] = qv;
        s += qv;
    }
    s += __shfl_xor_sync(0xffffffffu, s, 1);
    s += __shfl_xor_sync(0xffffffffu, s, 2);

    if (i >= jb && i < jb + 16) vals[i - jb] = -s;

    float4* out4 = (float4*)(Q + (size_t)tok * (VV * VV) + i * VV + jb);
#pragma unroll
    for (int q = 0; q < 4; ++q)
        out4[q] = make_float4(vals[q * 4], vals[q * 4 + 1],
                              vals[q * 4 + 2], vals[q * 4 + 3]);
}

// ---------------------------------------------------------------------------
// Launch (fork/join overlap: side stream for Wt/WT splits + GEMM2 + softmax)
// ---------------------------------------------------------------------------
#define SMEM_BIG  (2 * (2 * 128 * HROWB + 2 * 256 * HROWB))   // 221184
#define SMEM_SMALL (2 * (2 * 128 * HROWB + 2 * 64 * HROWB))   // 110592

extern "C" void kernel_launch(void* const* d_in, const int* in_sizes, int n_in,
                              void* d_out, int out_size)
{
    const float* hx = (const float*)d_in[0];   // (B,L,E)
    const float* Wd = (const float*)d_in[1];   // (E,E)
    const float* bd = (const float*)d_in[2];
    const float* lg = (const float*)d_in[3];
    const float* lb = (const float*)d_in[4];
    const float* Wt = (const float*)d_in[5];   // (V,E)
    const float* bt = (const float*)d_in[6];
    const float* WT = (const float*)d_in[7];   // (NT,E)
    const float* bT = (const float*)d_in[8];

    float* out = (float*)d_out;
    float* Q  = out;
    float* pi = out + (size_t)MM * VV * VV;

    float *hbuf, *thbuf;
    __half *hxh, *hh, *hl, *wdh, *wdl, *wth, *wtl, *wTh, *wTl;
    cudaGetSymbolAddress((void**)&hbuf,  g_h);
    cudaGetSymbolAddress((void**)&thbuf, g_theta);
    cudaGetSymbolAddress((void**)&hxh, g_hx_hi);
    cudaGetSymbolAddress((void**)&hh,  g_h_hi);   cudaGetSymbolAddress((void**)&hl,  g_h_lo);
    cudaGetSymbolAddress((void**)&wdh, g_Wd_hi);  cudaGetSymbolAddress((void**)&wdl, g_Wd_lo);
    cudaGetSymbolAddress((void**)&wth, g_Wt_hi);  cudaGetSymbolAddress((void**)&wtl, g_Wt_lo);
    cudaGetSymbolAddress((void**)&wTh, g_WT_hi);  cudaGetSymbolAddress((void**)&wTl, g_WT_lo);

    cudaFuncSetAttribute((const void*)gemm_hmma<1, 256, 4, 2>,
                         cudaFuncAttributeMaxDynamicSharedMemorySize, SMEM_BIG);
    cudaFuncSetAttribute((const void*)gemm_hmma<2, 256, 4, 2>,
                         cudaFuncAttributeMaxDynamicSharedMemorySize, SMEM_BIG);
    cudaFuncSetAttribute((const void*)gemm_hmma<0, 64, 2, 3>,
                         cudaFuncAttributeMaxDynamicSharedMemorySize, SMEM_SMALL);

    // side stream + events (created once; captured work identical every call)
    static cudaStream_t s1 = []{
        cudaStream_t s; cudaStreamCreateWithFlags(&s, cudaStreamNonBlocking); return s;
    }();
    static cudaEvent_t evFork = []{
        cudaEvent_t e; cudaEventCreateWithFlags(&e, cudaEventDisableTiming); return e;
    }();
    static cudaEvent_t evWT = []{
        cudaEvent_t e; cudaEventCreateWithFlags(&e, cudaEventDisableTiming); return e;
    }();
    static cudaEvent_t evLN = []{
        cudaEvent_t e; cudaEventCreateWithFlags(&e, cudaEventDisableTiming); return e;
    }();
    static cudaEvent_t evSM = []{
        cudaEvent_t e; cudaEventCreateWithFlags(&e, cudaEventDisableTiming); return e;
    }();

    // fork side stream
    cudaEventRecord(evFork, 0);
    cudaStreamWaitEvent(s1, evFork, 0);

    // side stream: Wt/WT splits (overlap with hx/Wd splits + GEMM1)
    split_kernel<<<(VV * EE / 8 + 255) / 256, 256, 0, s1>>>(Wt, wth, wtl, VV * EE / 8);
    split_kernel<<<(NTT * EE / 8 + 255) / 256, 256, 0, s1>>>(WT, wTh, wTl, NTT * EE / 8);
    cudaEventRecord(evWT, s1);

    // main stream: Wd/hx splits -> GEMM1 -> LN
    split_kernel<<<(EE * EE / 8 + 255) / 256, 256>>>(Wd, wdh, wdl, EE * EE / 8);
    split_hi_kernel<<<(MM * EE / 8 + 255) / 256, 256>>>(hx, hxh, MM * EE / 8);
    gemm_hmma<1, 256, 4, 2><<<dim3(MM / HBM, EE / 256), 512, SMEM_BIG>>>(
        hxh, hxh, wdh, wdl, bd, hbuf, EE, EE);
    ln_split_kernel<<<MM, 128>>>(hbuf, lg, lb, hh, hl);
    cudaEventRecord(evLN, 0);

    // side stream: GEMM2 + softmax (overlaps with GEMM3 on main)
    cudaStreamWaitEvent(s1, evLN, 0);
    gemm_hmma<0, 64, 2, 3><<<dim3(MM / HBM, 1), 512, SMEM_SMALL, s1>>>(
        hh, hl, wth, wtl, bt, pi, VV, EE);
    softmax_kernel<<<MM / 8, 256, 0, s1>>>(pi);
    cudaEventRecord(evSM, s1);

    // main stream: GEMM3 (needs WT split), then join, then qasm
    cudaStreamWaitEvent(0, evWT, 0);
    gemm_hmma<2, 256, 4, 2><<<dim3(MM / HBM, (NTT + 255) / 256), 512, SMEM_BIG>>>(
        hh, hh, wTh, wTl, bT, thbuf, NTT, EE);
    cudaStreamWaitEvent(0, evSM, 0);
    qasm_kernel<<<MM, 256>>>(thbuf, pi, Q);
}

// round 9
// speedup vs baseline: 3.8253x; 1.0427x over previous
#include <cuda_runtime.h>
#include <cuda_fp16.h>
#include <math.h>
#include <stdint.h>

// Problem constants
#define MM 8192           // B*L tokens
#define EE 1024
#define VV 64
#define NTT 2016
#define LN_EPS 1e-5f
#define MC (MM / 2)       // chunk size (tokens)

// ---------------------------------------------------------------------------
// Scratch (device globals; no dynamic allocation allowed)
// ---------------------------------------------------------------------------
__device__ float g_h[(size_t)MM * EE];          // gelu output (pre-LN)
__device__ float g_theta[(size_t)MM * NTT];     // softplus(Theta)
__device__ __half g_hx_hi[(size_t)MM * EE];
__device__ __half g_h_hi [(size_t)MM * EE], g_h_lo [(size_t)MM * EE];
__device__ __half g_Wd_hi[EE * EE],  g_Wd_lo[EE * EE];
__device__ __half g_Wt_hi[VV * EE],  g_Wt_lo[VV * EE];
__device__ __half g_WT_hi[NTT * EE], g_WT_lo[NTT * EE];

// ---------------------------------------------------------------------------
// PTX helpers
// ---------------------------------------------------------------------------
__device__ __forceinline__ uint32_t smem_u32(const void* p) {
    return (uint32_t)__cvta_generic_to_shared(p);
}
__device__ __forceinline__ void cp16(uint32_t dst, const void* src, int sz) {
    asm volatile("cp.async.cg.shared.global [%0], [%1], 16, %2;"
                 :: "r"(dst), "l"(src), "r"(sz));
}
__device__ __forceinline__ void cp_commit() {
    asm volatile("cp.async.commit_group;" ::: "memory");
}
template<int N> __device__ __forceinline__ void cp_wait() {
    asm volatile("cp.async.wait_group %0;" :: "n"(N) : "memory");
}
__device__ __forceinline__ void ldsm4(uint32_t* r, uint32_t a) {
    asm volatile("ldmatrix.sync.aligned.m8n8.x4.shared.b16 {%0,%1,%2,%3}, [%4];"
        : "=r"(r[0]), "=r"(r[1]), "=r"(r[2]), "=r"(r[3]) : "r"(a));
}
__device__ __forceinline__ void mma16816(float* c, const uint32_t* a,
                                         uint32_t b0, uint32_t b1) {
    asm volatile(
        "mma.sync.aligned.m16n8k16.row.col.f32.f16.f16.f32 "
        "{%0,%1,%2,%3}, {%4,%5,%6,%7}, {%8,%9}, {%0,%1,%2,%3};"
        : "+f"(c[0]), "+f"(c[1]), "+f"(c[2]), "+f"(c[3])
        : "r"(a[0]), "r"(a[1]), "r"(a[2]), "r"(a[3]), "r"(b0), "r"(b1));
}

// ---------------------------------------------------------------------------
// fp32 -> (fp16 hi, fp16 lo) split, 8 elems/thread (uint4 stores)
// ---------------------------------------------------------------------------
__global__ __launch_bounds__(256)
void split_kernel(const float* __restrict__ x, __half* __restrict__ hi,
                  __half* __restrict__ lo, int n8)
{
    int i = blockIdx.x * 256 + threadIdx.x;
    if (i >= n8) return;
    float4 a = ((const float4*)x)[i * 2];
    float4 b = ((const float4*)x)[i * 2 + 1];
    float vv[8] = {a.x, a.y, a.z, a.w, b.x, b.y, b.z, b.w};
    __half h[8], l[8];
#pragma unroll
    for (int k = 0; k < 8; ++k) {
        h[k] = __float2half_rn(vv[k]);
        l[k] = __float2half_rn(vv[k] - __half2float(h[k]));
    }
    ((uint4*)hi)[i] = *(uint4*)h;
    ((uint4*)lo)[i] = *(uint4*)l;
}

// fp32 -> fp16 hi only (for A operands of 2-term GEMMs)
__global__ __launch_bounds__(256)
void split_hi_kernel(const float* __restrict__ x, __half* __restrict__ hi, int n8)
{
    int i = blockIdx.x * 256 + threadIdx.x;
    if (i >= n8) return;
    float4 a = ((const float4*)x)[i * 2];
    float4 b = ((const float4*)x)[i * 2 + 1];
    float vv[8] = {a.x, a.y, a.z, a.w, b.x, b.y, b.z, b.w};
    __half h[8];
#pragma unroll
    for (int k = 0; k < 8; ++k) h[k] = __float2half_rn(vv[k]);
    ((uint4*)hi)[i] = *(uint4*)h;
}

// ---------------------------------------------------------------------------
// fp16 multi-term HMMA GEMM:  C[M,N] = epi(A[M,K] @ B[N,K]^T + bias[N])
// BM=128, BN template (256 big / 64 narrow), BK=64, 512 threads (16 warps).
// TERMS=3: Ah*Bh + Ah*Bl + Al*Bh ; TERMS=2: Ah*Bh + Ah*Bl
// cp.async double-buffered smem, padded 144B rows.
// EPI: 0 none, 1 exact gelu, 2 softplus
// ---------------------------------------------------------------------------
#define HBM 128
#define HBK 64
#define HROWB 144                 // 64 fp16 = 128B + 16B pad

template<int EPI, int BN, int WN, int TERMS>
__global__ __launch_bounds__(512, 1)
void gemm_hmma(const __half* __restrict__ Ah, const __half* __restrict__ Al,
               const __half* __restrict__ Bh, const __half* __restrict__ Bl,
               const float* __restrict__ bias, float* __restrict__ C,
               int N, int K)
{
    constexpr int WM  = 16 / WN;
    constexpr int WTM = HBM / WM;
    constexpr int WTN = BN / WN;
    constexpr int MT  = WTM / 16;
    constexpr int NJ  = WTN / 16;

    constexpr int A_BYTES = HBM * HROWB;
    constexpr int B_BYTES = BN * HROWB;
    constexpr int AHOFF = 0;
    constexpr int ALOFF = A_BYTES;
    constexpr int BHOFF = 2 * A_BYTES;
    constexpr int BLOFF = 2 * A_BYTES + B_BYTES;
    constexpr int STAGE = 2 * A_BYTES + 2 * B_BYTES;

    extern __shared__ char hsm[];
    const uint32_t sb = smem_u32(hsm);

    const int tid  = threadIdx.x;
    const int wid  = tid >> 5;
    const int lane = tid & 31;
    const int wmb  = (wid % WM) * WTM;
    const int wnb  = (wid / WM) * WTN;
    const int bm   = blockIdx.x * HBM;
    const int bn   = blockIdx.y * BN;

    auto issue_stage = [&](int kt) {
        const uint32_t st = sb + (kt & 1) * STAGE;
        const int k0 = kt * HBK;
#pragma unroll
        for (int it = 0; it < 2; ++it) {
            int c = tid + it * 512;
            int row = c >> 3, part = c & 7;
            uint32_t dst = (uint32_t)(row * HROWB + part * 16);
            size_t src = (size_t)(bm + row) * K + k0 + part * 8;
            cp16(st + AHOFF + dst, Ah + src, 16);
            if (TERMS == 3) cp16(st + ALOFF + dst, Al + src, 16);
        }
#pragma unroll
        for (int it = 0; it < BN / 64; ++it) {
            int c = tid + it * 512;
            int row = c >> 3, part = c & 7;
            int gn = bn + row;
            int valid = (gn < N) ? 16 : 0;
            int gnc = (gn < N) ? gn : 0;
            uint32_t dst = (uint32_t)(row * HROWB + part * 16);
            size_t src = (size_t)gnc * K + k0 + part * 8;
            cp16(st + BHOFF + dst, Bh + src, valid);
            cp16(st + BLOFF + dst, Bl + src, valid);
        }
        cp_commit();
    };

    float acc[MT][WTN / 8][4];
#pragma unroll
    for (int i = 0; i < MT; ++i)
#pragma unroll
        for (int j = 0; j < WTN / 8; ++j)
#pragma unroll
            for (int q = 0; q < 4; ++q) acc[i][j][q] = 0.0f;

    issue_stage(0);

    const int nk = K / HBK;
    const int a_row = lane & 15;
    const int a_cb  = (lane >> 4) * 16;
    const int b_row = ((lane >> 4) ? 8 : 0) + (lane & 7);
    const int b_cb  = (((lane >> 3) & 1) ? 16 : 0);

    for (int kt = 0; kt < nk; ++kt) {
        if (kt + 1 < nk) { issue_stage(kt + 1); cp_wait<1>(); }
        else             { cp_wait<0>(); }
        __syncthreads();
        const uint32_t st = sb + (kt & 1) * STAGE;

#pragma unroll
        for (int ks = 0; ks < 4; ++ks) {
            uint32_t aH[MT][4], aL[MT][4];
#pragma unroll
            for (int mt = 0; mt < MT; ++mt) {
                const uint32_t ao = st + (uint32_t)((wmb + mt * 16 + a_row) * HROWB
                                                    + ks * 32 + a_cb);
                ldsm4(aH[mt], ao + AHOFF);
                if (TERMS == 3) ldsm4(aL[mt], ao + ALOFF);
            }
#pragma unroll
            for (int jj = 0; jj < NJ; ++jj) {
                const uint32_t bo = st + (uint32_t)((wnb + jj * 16 + b_row) * HROWB
                                                    + ks * 32 + b_cb);
                uint32_t bH[4], bL[4];
                ldsm4(bH, bo + BHOFF);
                ldsm4(bL, bo + BLOFF);
#pragma unroll
                for (int mt = 0; mt < MT; ++mt) {
#pragma unroll
                    for (int sub = 0; sub < 2; ++sub) {
                        float* c = acc[mt][jj * 2 + sub];
                        mma16816(c, aH[mt], bH[sub * 2], bH[sub * 2 + 1]);
                        mma16816(c, aH[mt], bL[sub * 2], bL[sub * 2 + 1]);
                        if (TERMS == 3)
                            mma16816(c, aL[mt], bH[sub * 2], bH[sub * 2 + 1]);
                    }
                }
            }
        }
        __syncthreads();
    }

    // epilogue
#pragma unroll
    for (int mt = 0; mt < MT; ++mt) {
        const int row = bm + wmb + mt * 16 + (lane >> 2);
#pragma unroll
        for (int nt = 0; nt < WTN / 8; ++nt) {
            const int col = bn + wnb + nt * 8 + (lane & 3) * 2;
            if (col < N) {
                const float b0 = bias[col], b1 = bias[col + 1];
                float vals[4];
                vals[0] = acc[mt][nt][0] + b0;
                vals[1] = acc[mt][nt][1] + b1;
                vals[2] = acc[mt][nt][2] + b0;
                vals[3] = acc[mt][nt][3] + b1;
#pragma unroll
                for (int q = 0; q < 4; ++q) {
                    float x = vals[q];
                    if (EPI == 1) {
                        x = 0.5f * x * (1.0f + erff(x * 0.70710678118654752440f));
                    } else if (EPI == 2) {
                        x = fmaxf(x, 0.0f) + log1pf(expf(-fabsf(x)));
                    }
                    vals[q] = x;
                }
                *(float2*)&C[(size_t)row * N + col]       = make_float2(vals[0], vals[1]);
                *(float2*)&C[(size_t)(row + 8) * N + col] = make_float2(vals[2], vals[3]);
            }
        }
    }
}

// ---------------------------------------------------------------------------
// LayerNorm over rows of E=1024, fused with fp16 hi/lo split of the output.
// ---------------------------------------------------------------------------
__global__ __launch_bounds__(128)
void ln_split_kernel(const float* __restrict__ h, const float* __restrict__ g,
                     const float* __restrict__ b,
                     __half* __restrict__ hi, __half* __restrict__ lo)
{
    const int row = blockIdx.x;
    const int tid = threadIdx.x;
    const int wid = tid >> 5;
    const float* p = h + (size_t)row * EE;

    float4 v0 = ((const float4*)p)[tid * 2];
    float4 v1 = ((const float4*)p)[tid * 2 + 1];
    float v[8] = {v0.x, v0.y, v0.z, v0.w, v1.x, v1.y, v1.z, v1.w};

    __shared__ float red_a[4], red_b[4];

    float s = 0.0f;
#pragma unroll
    for (int k = 0; k < 8; ++k) s += v[k];
#pragma unroll
    for (int o = 16; o; o >>= 1) s += __shfl_xor_sync(0xffffffffu, s, o);
    if ((tid & 31) == 0) red_a[wid] = s;
    __syncthreads();
    const float mu = (red_a[0] + red_a[1] + red_a[2] + red_a[3]) * (1.0f / EE);

    float d[8];
    float s2 = 0.0f;
#pragma unroll
    for (int k = 0; k < 8; ++k) { d[k] = v[k] - mu; s2 += d[k] * d[k]; }
#pragma unroll
    for (int o = 16; o; o >>= 1) s2 += __shfl_xor_sync(0xffffffffu, s2, o);
    if ((tid & 31) == 0) red_b[wid] = s2;
    __syncthreads();
    const float rstd = rsqrtf((red_b[0] + red_b[1] + red_b[2] + red_b[3]) * (1.0f / EE)
                              + LN_EPS);

    const int c = tid * 8;
    float4 g0 = *(const float4*)&g[c], g1 = *(const float4*)&g[c + 4];
    float4 b0 = *(const float4*)&b[c], b1 = *(const float4*)&b[c + 4];
    float gg[8] = {g0.x, g0.y, g0.z, g0.w, g1.x, g1.y, g1.z, g1.w};
    float bb[8] = {b0.x, b0.y, b0.z, b0.w, b1.x, b1.y, b1.z, b1.w};

    __half hb[8], lb8[8];
#pragma unroll
    for (int k = 0; k < 8; ++k) {
        float o = d[k] * rstd * gg[k] + bb[k];
        hb[k]  = __float2half_rn(o);
        lb8[k] = __float2half_rn(o - __half2float(hb[k]));
    }
    ((uint4*)(hi + (size_t)row * EE))[tid] = *(uint4*)hb;
    ((uint4*)(lo + (size_t)row * EE))[tid] = *(uint4*)lb8;
}

// ---------------------------------------------------------------------------
// Softmax (in-place) over rows of V=64. One warp per row, 8 rows per block.
// ---------------------------------------------------------------------------
__global__ __launch_bounds__(256)
void softmax_kernel(float* __restrict__ logits)
{
    const int row = blockIdx.x * 8 + (threadIdx.x >> 5);
    const int lane = threadIdx.x & 31;
    float* p = logits + (size_t)row * VV;

    float2 v = *(const float2*)&p[lane * 2];
    float m = fmaxf(v.x, v.y);
#pragma unroll
    for (int o = 16; o; o >>= 1) m = fmaxf(m, __shfl_xor_sync(0xffffffffu, m, o));
    float e0 = expf(v.x - m), e1 = expf(v.y - m);
    float s = e0 + e1;
#pragma unroll
    for (int o = 16; o; o >>= 1) s += __shfl_xor_sync(0xffffffffu, s, o);
    float inv = 1.0f / s;
    float2 o2; o2.x = e0 * inv; o2.y = e1 * inv;
    *(float2*)&p[lane * 2] = o2;
}

// ---------------------------------------------------------------------------
// Q assembly (float4 stores)
// ---------------------------------------------------------------------------
__global__ __launch_bounds__(256)
void qasm_kernel(const float* __restrict__ theta, const float* __restrict__ pi,
                 float* __restrict__ Q)
{
    const int tok = blockIdx.x;
    __shared__ float th[NTT];
    __shared__ float spi[VV];
    __shared__ float rspi[VV];

    const int tid = threadIdx.x;
    const float* tp = theta + (size_t)tok * NTT;
    for (int i = tid; i < NTT / 4; i += 256)
        ((float4*)th)[i] = ((const float4*)tp)[i];
    if (tid < VV) {
        float p = pi[(size_t)tok * VV + tid];
        float sp = sqrtf(p);
        spi[tid] = sp;
        rspi[tid] = 1.0f / sp;
    }
    __syncthreads();

    const int i = tid >> 2;
    const int jb = (tid & 3) * 16;
    const float ri = rspi[i];
    const int offi = i * (127 - i) / 2;

    float vals[16];
    float s = 0.0f;
#pragma unroll
    for (int jj = 0; jj < 16; ++jj) {
        int j = jb + jj;
        float sv;
        if (j == i)      sv = 0.0f;
        else if (i < j)  sv = th[offi + j - i - 1];
        else             sv = th[j * (127 - j) / 2 + i - j - 1];
        float qv = sv * spi[j] * ri;
        vals[jj] = qv;
        s += qv;
    }
    s += __shfl_xor_sync(0xffffffffu, s, 1);
    s += __shfl_xor_sync(0xffffffffu, s, 2);

    if (i >= jb && i < jb + 16) vals[i - jb] = -s;

    float4* out4 = (float4*)(Q + (size_t)tok * (VV * VV) + i * VV + jb);
#pragma unroll
    for (int q = 0; q < 4; ++q)
        out4[q] = make_float4(vals[q * 4], vals[q * 4 + 1],
                              vals[q * 4 + 2], vals[q * 4 + 3]);
}

// ---------------------------------------------------------------------------
// Launch: 2-chunk software pipeline across two streams.
// ---------------------------------------------------------------------------
#define SMEM_BIG  (2 * (2 * 128 * HROWB + 2 * 256 * HROWB))   // 221184
#define SMEM_SMALL (2 * (2 * 128 * HROWB + 2 * 64 * HROWB))   // 110592

static cudaEvent_t mk_event() {
    cudaEvent_t e; cudaEventCreateWithFlags(&e, cudaEventDisableTiming); return e;
}

extern "C" void kernel_launch(void* const* d_in, const int* in_sizes, int n_in,
                              void* d_out, int out_size)
{
    const float* hx = (const float*)d_in[0];   // (B,L,E)
    const float* Wd = (const float*)d_in[1];   // (E,E)
    const float* bd = (const float*)d_in[2];
    const float* lg = (const float*)d_in[3];
    const float* lb = (const float*)d_in[4];
    const float* Wt = (const float*)d_in[5];   // (V,E)
    const float* bt = (const float*)d_in[6];
    const float* WT = (const float*)d_in[7];   // (NT,E)
    const float* bT = (const float*)d_in[8];

    float* out = (float*)d_out;
    float* Q  = out;
    float* pi = out + (size_t)MM * VV * VV;

    float *hbuf, *thbuf;
    __half *hxh, *hh, *hl, *wdh, *wdl, *wth, *wtl, *wTh, *wTl;
    cudaGetSymbolAddress((void**)&hbuf,  g_h);
    cudaGetSymbolAddress((void**)&thbuf, g_theta);
    cudaGetSymbolAddress((void**)&hxh, g_hx_hi);
    cudaGetSymbolAddress((void**)&hh,  g_h_hi);   cudaGetSymbolAddress((void**)&hl,  g_h_lo);
    cudaGetSymbolAddress((void**)&wdh, g_Wd_hi);  cudaGetSymbolAddress((void**)&wdl, g_Wd_lo);
    cudaGetSymbolAddress((void**)&wth, g_Wt_hi);  cudaGetSymbolAddress((void**)&wtl, g_Wt_lo);
    cudaGetSymbolAddress((void**)&wTh, g_WT_hi);  cudaGetSymbolAddress((void**)&wTl, g_WT_lo);

    cudaFuncSetAttribute((const void*)gemm_hmma<1, 256, 4, 2>,
                         cudaFuncAttributeMaxDynamicSharedMemorySize, SMEM_BIG);
    cudaFuncSetAttribute((const void*)gemm_hmma<2, 256, 4, 2>,
                         cudaFuncAttributeMaxDynamicSharedMemorySize, SMEM_BIG);
    cudaFuncSetAttribute((const void*)gemm_hmma<0, 64, 2, 3>,
                         cudaFuncAttributeMaxDynamicSharedMemorySize, SMEM_SMALL);

    static cudaStream_t s1 = []{
        cudaStream_t s; cudaStreamCreateWithFlags(&s, cudaStreamNonBlocking); return s;
    }();
    static cudaEvent_t evFork = mk_event();
    static cudaEvent_t evX1   = mk_event();   // split_hx c1 done
    static cudaEvent_t evWT   = mk_event();   // weight splits done (s1)
    static cudaEvent_t e10    = mk_event();   // GEMM1 c0
    static cudaEvent_t e11    = mk_event();   // GEMM1 c1
    static cudaEvent_t eL0    = mk_event();   // LN c0
    static cudaEvent_t eL1    = mk_event();   // LN c1
    static cudaEvent_t eS1    = mk_event();   // softmax c1
    static cudaEvent_t e30    = mk_event();   // GEMM3 c0
    static cudaEvent_t eQ0    = mk_event();   // qasm c0

    // offsets for chunk c (c=0,1)
    const size_t offE  = (size_t)MC * EE;     // h-space rows
    const size_t offT  = (size_t)MC * NTT;    // theta rows
    const size_t offV  = (size_t)MC * VV;     // pi rows
    const size_t offQ  = (size_t)MC * VV * VV;

    // fork
    cudaEventRecord(evFork, 0);
    cudaStreamWaitEvent(s1, evFork, 0);

    // S1: split hx c1, then weight splits for GEMM2/GEMM3
    split_hi_kernel<<<(MC * EE / 8 + 255) / 256, 256, 0, s1>>>(
        hx + offE, hxh + offE, MC * EE / 8);
    cudaEventRecord(evX1, s1);
    split_kernel<<<(VV * EE / 8 + 255) / 256, 256, 0, s1>>>(Wt, wth, wtl, VV * EE / 8);
    split_kernel<<<(NTT * EE / 8 + 255) / 256, 256, 0, s1>>>(WT, wTh, wTl, NTT * EE / 8);
    cudaEventRecord(evWT, s1);

    // S0: Wd split + hx c0 split -> GEMM1 c0 -> GEMM1 c1
    split_kernel<<<(EE * EE / 8 + 255) / 256, 256>>>(Wd, wdh, wdl, EE * EE / 8);
    split_hi_kernel<<<(MC * EE / 8 + 255) / 256, 256>>>(hx, hxh, MC * EE / 8);
    gemm_hmma<1, 256, 4, 2><<<dim3(MC / HBM, EE / 256), 512, SMEM_BIG>>>(
        hxh, hxh, wdh, wdl, bd, hbuf, EE, EE);
    cudaEventRecord(e10, 0);
    cudaStreamWaitEvent(0, evX1, 0);
    gemm_hmma<1, 256, 4, 2><<<dim3(MC / HBM, EE / 256), 512, SMEM_BIG>>>(
        hxh + offE, hxh + offE, wdh, wdl, bd, hbuf + offE, EE, EE);
    cudaEventRecord(e11, 0);

    // S1: LN per chunk (c0 overlaps GEMM1 c1), then GEMM2 + softmax per chunk
    cudaStreamWaitEvent(s1, e10, 0);
    ln_split_kernel<<<MC, 128, 0, s1>>>(hbuf, lg, lb, hh, hl);
    cudaEventRecord(eL0, s1);
    cudaStreamWaitEvent(s1, e11, 0);
    ln_split_kernel<<<MC, 128, 0, s1>>>(hbuf + offE, lg, lb, hh + offE, hl + offE);
    cudaEventRecord(eL1, s1);
    gemm_hmma<0, 64, 2, 3><<<dim3(MC / HBM, 1), 512, SMEM_SMALL, s1>>>(
        hh, hl, wth, wtl, bt, pi, VV, EE);
    gemm_hmma<0, 64, 2, 3><<<dim3(MC / HBM, 1), 512, SMEM_SMALL, s1>>>(
        hh + offE, hl + offE, wth, wtl, bt, pi + offV, VV, EE);
    softmax_kernel<<<MC / 8, 256, 0, s1>>>(pi);
    softmax_kernel<<<MC / 8, 256, 0, s1>>>(pi + offV);
    cudaEventRecord(eS1, s1);

    // S0: GEMM3 per chunk
    cudaStreamWaitEvent(0, evWT, 0);
    cudaStreamWaitEvent(0, eL0, 0);
    gemm_hmma<2, 256, 4, 2><<<dim3(MC / HBM, (NTT + 255) / 256), 512, SMEM_BIG>>>(
        hh, hh, wTh, wTl, bT, thbuf, NTT, EE);
    cudaEventRecord(e30, 0);
    cudaStreamWaitEvent(0, eL1, 0);
    gemm_hmma<2, 256, 4, 2><<<dim3(MC / HBM, (NTT + 255) / 256), 512, SMEM_BIG>>>(
        hh + offE, hh + offE, wTh, wTl, bT, thbuf + offT, NTT, EE);

    // S1: qasm c0 (overlaps GEMM3 c1 on S0)
    cudaStreamWaitEvent(s1, e30, 0);
    qasm_kernel<<<MC, 256, 0, s1>>>(thbuf, pi, Q);
    cudaEventRecord(eQ0, s1);

    // S0: qasm c1 after GEMM3 c1 (program order) + softmax c1; then join
    cudaStreamWaitEvent(0, eS1, 0);
    qasm_kernel<<<MC, 256>>>(thbuf + offT, pi + offV, Q + offQ);
    cudaStreamWaitEvent(0, eQ0, 0);
}